// round 2
// baseline (speedup 1.0000x reference)
#include <cuda_runtime.h>
#include <math.h>
#include <stdint.h>

// Problem dims (fixed)
#define BB   256      // batch
#define LL   64       // seq len
#define DD   256      // input dim
#define HH   512      // hidden
#define G4   2048     // 4*H

// -------- scratch (device globals: allocation-free) --------
__device__ float g_WI[(size_t)BB * LL * DD];        // 16 MB  : a * x, all timesteps
__device__ float g_Gx[(size_t)BB * LL * G4];        // 128 MB : WI @ W_ih^T + biases
__device__ float g_gates[(size_t)BB * G4];          // 2 MB   : per-step gates
__device__ float g_c[(size_t)BB * HH];              // 0.5 MB : cell state

// ============================================================
// Kernel 1: ex = x^T @ Wx ; a = softmax_d(ex) ; att = a (all t) ; WI = a*x
// softmax(ex + const_per_row) == softmax(ex), so attention is
// timestep-independent and decoupled from the recurrence.
// ============================================================
__global__ void attn_kernel(const float* __restrict__ x,
                            const float* __restrict__ Wa,
                            float* __restrict__ att)
{
    __shared__ float wx[LL];
    __shared__ float red[DD];
    const int b = blockIdx.x;
    const int d = threadIdx.x;     // 0..255

    if (d < LL) wx[d] = Wa[2 * HH + d];
    __syncthreads();

    const float* xb = x + (size_t)b * LL * DD;
    float ex = 0.f;
#pragma unroll
    for (int l = 0; l < LL; ++l)
        ex += xb[l * DD + d] * wx[l];

    // block max
    red[d] = ex; __syncthreads();
    for (int s = DD / 2; s > 0; s >>= 1) {
        if (d < s) red[d] = fmaxf(red[d], red[d + s]);
        __syncthreads();
    }
    const float mx = red[0];
    __syncthreads();

    const float e = expf(ex - mx);
    red[d] = e; __syncthreads();
    for (int s = DD / 2; s > 0; s >>= 1) {
        if (d < s) red[d] += red[d + s];
        __syncthreads();
    }
    const float a = e / red[0];

    float* attb = att + (size_t)b * LL * DD;
    float* wib  = g_WI + (size_t)b * LL * DD;
#pragma unroll 4
    for (int t = 0; t < LL; ++t) {
        attb[t * DD + d] = a;
        wib[t * DD + d]  = a * xb[t * DD + d];
    }
}

// ============================================================
// SGEMM: C[M,N] = A[M,K] @ B[N,K]^T (+ bias1[n] + bias2[n]) (+ Cadd[m,n])
// BM=BN=64, BK=16, 256 threads, 4x4 register tile per thread.
// A has row stride lda; B row-major (ldb = K); Cadd row stride ldadd.
// Requires M%64==0, N%64==0, K%16==0 (true for all call sites).
// ============================================================
__global__ void sgemm64(int M, int N, int K,
                        const float* __restrict__ A, int lda,
                        const float* __restrict__ Bw,
                        const float* __restrict__ bias1,
                        const float* __restrict__ bias2,
                        const float* __restrict__ Cadd, int ldadd,
                        float* __restrict__ C, int ldc)
{
    const int BM = 64, BN = 64, BK = 16;
    __shared__ __align__(16) float As[BK][BM + 4];
    __shared__ __align__(16) float Bs[BK][BN + 4];

    const int tid = threadIdx.x;       // 0..255
    const int tx  = tid & 15;          // n-dir (16)
    const int ty  = tid >> 4;          // m-dir (16)
    const int m0  = blockIdx.y * BM;
    const int n0  = blockIdx.x * BN;

    // tile-load indices: one float4 per thread per tile
    const int lrow = tid >> 2;             // 0..63
    const int lk   = (tid & 3) * 4;        // 0,4,8,12

    float acc[4][4] = {};

    for (int k0 = 0; k0 < K; k0 += BK) {
        float4 av = *(const float4*)(A  + (size_t)(m0 + lrow) * lda + k0 + lk);
        float4 bv = *(const float4*)(Bw + (size_t)(n0 + lrow) * K   + k0 + lk);
        As[lk + 0][lrow] = av.x; As[lk + 1][lrow] = av.y;
        As[lk + 2][lrow] = av.z; As[lk + 3][lrow] = av.w;
        Bs[lk + 0][lrow] = bv.x; Bs[lk + 1][lrow] = bv.y;
        Bs[lk + 2][lrow] = bv.z; Bs[lk + 3][lrow] = bv.w;
        __syncthreads();

#pragma unroll
        for (int kk = 0; kk < BK; ++kk) {
            const float4 af = *(const float4*)&As[kk][ty * 4];
            const float4 bf = *(const float4*)&Bs[kk][tx * 4];
            const float am[4] = {af.x, af.y, af.z, af.w};
            const float bn[4] = {bf.x, bf.y, bf.z, bf.w};
#pragma unroll
            for (int i = 0; i < 4; ++i)
#pragma unroll
                for (int j = 0; j < 4; ++j)
                    acc[i][j] += am[i] * bn[j];
        }
        __syncthreads();
    }

#pragma unroll
    for (int i = 0; i < 4; ++i) {
        const int m = m0 + ty * 4 + i;
        float4 out;
        float* op = &out.x;
#pragma unroll
        for (int j = 0; j < 4; ++j) {
            const int n = n0 + tx * 4 + j;
            float v = acc[i][j];
            if (bias1) v += bias1[n];
            if (bias2) v += bias2[n];
            if (Cadd)  v += Cadd[(size_t)m * ldadd + n];
            op[j] = v;
        }
        *(float4*)(C + (size_t)m * ldc + n0 + tx * 4) = out;
    }
}

// ============================================================
// LSTM cell: c,h update + enc write. One thread per (b,u).
// ============================================================
__global__ void lstm_cell(const float* __restrict__ c_src,
                          float* __restrict__ enc, int t)
{
    const int idx = blockIdx.x * blockDim.x + threadIdx.x;  // 0..B*H
    const int b = idx >> 9;      // / 512
    const int u = idx & (HH - 1);

    const float* gb = g_gates + (size_t)b * G4;
    const float gi = gb[u];
    const float gf = gb[HH + u];
    const float gg = gb[2 * HH + u];
    const float go = gb[3 * HH + u];

    const float c  = c_src[idx];
    const float si = 1.f / (1.f + expf(-gi));
    const float sf = 1.f / (1.f + expf(-gf));
    const float so = 1.f / (1.f + expf(-go));
    const float cn = sf * c + si * tanhf(gg);
    const float hn = so * tanhf(cn);

    g_c[idx] = cn;
    enc[((size_t)b * LL + t) * HH + u] = hn;
}

// ============================================================
// Launch
// ============================================================
extern "C" void kernel_launch(void* const* d_in, const int* in_sizes, int n_in,
                              void* d_out, int out_size)
{
    (void)in_sizes; (void)n_in; (void)out_size;
    const float* x   = (const float*)d_in[0];
    const float* h0  = (const float*)d_in[1];
    const float* c0  = (const float*)d_in[2];
    const float* Wih = (const float*)d_in[3];
    const float* Whh = (const float*)d_in[4];
    const float* bih = (const float*)d_in[5];
    const float* bhh = (const float*)d_in[6];
    const float* Wa  = (const float*)d_in[7];
    // d_in[8] = ba: cancels inside softmax, never read.

    float* att = (float*)d_out;                       // (B, L, D)
    float* enc = att + (size_t)BB * LL * DD;          // (B, L, H)

    float *wi, *gx, *gates, *cbuf;
    cudaGetSymbolAddress((void**)&wi,    g_WI);
    cudaGetSymbolAddress((void**)&gx,    g_Gx);
    cudaGetSymbolAddress((void**)&gates, g_gates);
    cudaGetSymbolAddress((void**)&cbuf,  g_c);

    // 1) attention weights + att output + WI scratch
    attn_kernel<<<BB, DD>>>(x, Wa, att);

    // 2) big parallel input projection: Gx = WI @ W_ih^T + b_ih + b_hh
    {
        dim3 grid(G4 / 64, (BB * LL) / 64);   // (32, 256)
        sgemm64<<<grid, 256>>>(BB * LL, G4, DD,
                               wi, DD,
                               Wih,
                               bih, bhh,
                               nullptr, 0,
                               gx, G4);
    }

    // 3) recurrence: per step, gates = Gx[:,t,:] + h @ W_hh^T ; LSTM cell
    for (int t = 0; t < LL; ++t) {
        const float* hprev = (t == 0) ? h0 : (enc + (size_t)(t - 1) * HH);
        const int    ldh   = (t == 0) ? HH : LL * HH;
        dim3 grid(G4 / 64, BB / 64);          // (32, 4)
        sgemm64<<<grid, 256>>>(BB, G4, HH,
                               hprev, ldh,
                               Whh,
                               nullptr, nullptr,
                               gx + (size_t)t * G4, LL * G4,
                               gates, G4);

        const float* csrc = (t == 0) ? c0 : cbuf;
        lstm_cell<<<(BB * HH) / 256, 256>>>(csrc, enc, t);
    }
}

// round 3
// speedup vs baseline: 1.8320x; 1.8320x over previous
#include <cuda_runtime.h>
#include <math.h>
#include <stdint.h>

// Problem dims (fixed)
#define BB   256      // batch
#define LL   64       // seq len
#define DD   256      // input dim
#define HH   512      // hidden
#define G4   2048     // 4*H

// -------- scratch (device globals: allocation-free) --------
__device__ float g_WI[(size_t)BB * LL * DD];        // 16 MB  : a * x, all timesteps
__device__ float g_Gx[(size_t)BB * LL * G4];        // 128 MB : WI @ W_ih^T + biases
__device__ float g_c[(size_t)BB * HH];              // 0.5 MB : cell state

// ---------- tf32 helpers ----------
__device__ __forceinline__ uint32_t f2tf32(float f) {
    uint32_t u;
    asm("cvt.rna.tf32.f32 %0, %1;" : "=r"(u) : "f"(f));
    return u;
}

__device__ __forceinline__ void mma8(float* c,
                                     uint32_t a0, uint32_t a1, uint32_t a2, uint32_t a3,
                                     uint32_t b0, uint32_t b1)
{
    asm volatile("mma.sync.aligned.m16n8k8.row.col.f32.tf32.tf32.f32 "
                 "{%0,%1,%2,%3},{%4,%5,%6,%7},{%8,%9},{%0,%1,%2,%3};"
                 : "+f"(c[0]), "+f"(c[1]), "+f"(c[2]), "+f"(c[3])
                 : "r"(a0), "r"(a1), "r"(a2), "r"(a3), "r"(b0), "r"(b1));
}

// ============================================================
// Kernel 1: a = softmax_d(x^T @ Wx); att = a (all t); WI = a*x
// (recurrent term is constant over the softmax axis -> cancels)
// ============================================================
__global__ void attn_kernel(const float* __restrict__ x,
                            const float* __restrict__ Wa,
                            float* __restrict__ att)
{
    __shared__ float wx[LL];
    __shared__ float red[DD];
    const int b = blockIdx.x;
    const int d = threadIdx.x;     // 0..255

    if (d < LL) wx[d] = Wa[2 * HH + d];
    __syncthreads();

    const float* xb = x + (size_t)b * LL * DD;
    float ex = 0.f;
#pragma unroll
    for (int l = 0; l < LL; ++l)
        ex += xb[l * DD + d] * wx[l];

    red[d] = ex; __syncthreads();
    for (int s = DD / 2; s > 0; s >>= 1) {
        if (d < s) red[d] = fmaxf(red[d], red[d + s]);
        __syncthreads();
    }
    const float mx = red[0];
    __syncthreads();

    const float e = expf(ex - mx);
    red[d] = e; __syncthreads();
    for (int s = DD / 2; s > 0; s >>= 1) {
        if (d < s) red[d] += red[d + s];
        __syncthreads();
    }
    const float a = e / red[0];

    float* attb = att + (size_t)b * LL * DD;
    float* wib  = g_WI + (size_t)b * LL * DD;
#pragma unroll 4
    for (int t = 0; t < LL; ++t) {
        attb[t * DD + d] = a;
        wib[t * DD + d]  = a * xb[t * DD + d];
    }
}

// ============================================================
// Kernel 2: Gx[16384,2048] = WI[16384,256] @ Wih[2048,256]^T + b_ih + b_hh
// tf32 mma, BM=128 BN=64 BK=32, 8 warps (4x2), warp tile 32x32.
// ============================================================
__global__ __launch_bounds__(256) void gemm_xproj(
    const float* __restrict__ A,
    const float* __restrict__ Bw,
    const float* __restrict__ b1,
    const float* __restrict__ b2,
    float* __restrict__ C)
{
    __shared__ float As[128 * 36];
    __shared__ float Bs[64 * 36];

    const int tid  = threadIdx.x;
    const int lane = tid & 31, warp = tid >> 5;
    const int qid  = lane >> 2, tig = lane & 3;
    const int wm   = warp >> 1;      // 0..3  -> rows wm*32
    const int wn   = warp & 1;       // 0..1  -> cols wn*32
    const int m0   = blockIdx.y * 128;
    const int n0   = blockIdx.x * 64;

    const int lr = tid >> 3;         // 0..31
    const int lk = (tid & 7) * 4;    // 0..28

    const float* aptr = A  + (size_t)(m0 + lr) * DD + lk;
    const float* bptr = Bw + (size_t)(n0 + lr) * DD + lk;

    float4 pa[4], pb[2];
#pragma unroll
    for (int i = 0; i < 4; ++i) pa[i] = *(const float4*)(aptr + (size_t)i * 32 * DD);
#pragma unroll
    for (int i = 0; i < 2; ++i) pb[i] = *(const float4*)(bptr + (size_t)i * 32 * DD);

    float acc[2][4][4] = {};

    for (int k0 = 0; k0 < DD; k0 += 32) {
#pragma unroll
        for (int i = 0; i < 4; ++i) {
            float* d = &As[(lr + i * 32) * 36 + lk];
            d[0] = __uint_as_float(f2tf32(pa[i].x));
            d[1] = __uint_as_float(f2tf32(pa[i].y));
            d[2] = __uint_as_float(f2tf32(pa[i].z));
            d[3] = __uint_as_float(f2tf32(pa[i].w));
        }
#pragma unroll
        for (int i = 0; i < 2; ++i) {
            float* d = &Bs[(lr + i * 32) * 36 + lk];
            d[0] = __uint_as_float(f2tf32(pb[i].x));
            d[1] = __uint_as_float(f2tf32(pb[i].y));
            d[2] = __uint_as_float(f2tf32(pb[i].z));
            d[3] = __uint_as_float(f2tf32(pb[i].w));
        }
        __syncthreads();

        if (k0 + 32 < DD) {
#pragma unroll
            for (int i = 0; i < 4; ++i) pa[i] = *(const float4*)(aptr + k0 + 32 + (size_t)i * 32 * DD);
#pragma unroll
            for (int i = 0; i < 2; ++i) pb[i] = *(const float4*)(bptr + k0 + 32 + (size_t)i * 32 * DD);
        }

#pragma unroll
        for (int kk = 0; kk < 4; ++kk) {
            uint32_t af[2][4], bf[4][2];
#pragma unroll
            for (int mt = 0; mt < 2; ++mt) {
                const float* s = &As[(wm * 32 + mt * 16 + qid) * 36 + kk * 8 + tig];
                af[mt][0] = __float_as_uint(s[0]);
                af[mt][1] = __float_as_uint(s[8 * 36]);
                af[mt][2] = __float_as_uint(s[4]);
                af[mt][3] = __float_as_uint(s[8 * 36 + 4]);
            }
#pragma unroll
            for (int nt = 0; nt < 4; ++nt) {
                const float* s = &Bs[(wn * 32 + nt * 8 + qid) * 36 + kk * 8 + tig];
                bf[nt][0] = __float_as_uint(s[0]);
                bf[nt][1] = __float_as_uint(s[4]);
            }
#pragma unroll
            for (int mt = 0; mt < 2; ++mt)
#pragma unroll
                for (int nt = 0; nt < 4; ++nt)
                    mma8(acc[mt][nt], af[mt][0], af[mt][1], af[mt][2], af[mt][3],
                         bf[nt][0], bf[nt][1]);
        }
        __syncthreads();
    }

#pragma unroll
    for (int mt = 0; mt < 2; ++mt) {
        const int m = m0 + wm * 32 + mt * 16 + qid;
#pragma unroll
        for (int nt = 0; nt < 4; ++nt) {
            const int n = n0 + wn * 32 + nt * 8 + 2 * tig;
            const float bb0 = b1[n] + b2[n];
            const float bb1 = b1[n + 1] + b2[n + 1];
            float2 o0 = {acc[mt][nt][0] + bb0, acc[mt][nt][1] + bb1};
            float2 o1 = {acc[mt][nt][2] + bb0, acc[mt][nt][3] + bb1};
            *(float2*)(C + (size_t)m * G4 + n)       = o0;
            *(float2*)(C + (size_t)(m + 8) * G4 + n) = o1;
        }
    }
}

// ============================================================
// Kernel 3 (per step): fused  gates = Gx[:,t,:] + h @ Whh^T ; LSTM cell.
// Block: 64 batch x 32 units, computes ALL 4 gates (N=128 eff), K=512.
// 8 warps: wm = warp>>2 (m half), gate = warp&3. Warp tile 32x32.
// Epilogue exchanges gates through smem, applies cell, writes c & enc.
// ============================================================
__global__ __launch_bounds__(256) void rec_step(
    const float* __restrict__ hprev, int ldh,
    const float* __restrict__ csrc,
    const float* __restrict__ Whh,
    const float* __restrict__ Gx,
    float* __restrict__ enc,
    int t)
{
    __shared__ float smem[4 * 64 * 33];      // 33.8 KB; As/Bs overlap Gt
    float* As = smem;                        // 64*36  = 2304 floats
    float* Bs = smem + 64 * 36;              // 128*36 = 4608 floats

    const int tid  = threadIdx.x;
    const int lane = tid & 31, warp = tid >> 5;
    const int qid  = lane >> 2, tig = lane & 3;
    const int wm   = warp >> 2;              // 0..1
    const int gate = warp & 3;               // 0..3
    const int u0   = blockIdx.x * 32;
    const int m0   = blockIdx.y * 64;

    const int lr = tid >> 3;                 // 0..31
    const int lk = (tid & 7) * 4;

    const float* aptr = hprev + (size_t)(m0 + lr) * ldh + lk;
    const float* bptr[4];
#pragma unroll
    for (int i = 0; i < 4; ++i) {
        const int r = lr + i * 32;           // 0..127
        bptr[i] = Whh + (size_t)((r >> 5) * HH + u0 + (r & 31)) * HH + lk;
    }

    float4 pa[2], pb[4];
    pa[0] = *(const float4*)(aptr);
    pa[1] = *(const float4*)(aptr + (size_t)32 * ldh);
#pragma unroll
    for (int i = 0; i < 4; ++i) pb[i] = *(const float4*)(bptr[i]);

    float acc[2][4][4] = {};

    for (int k0 = 0; k0 < HH; k0 += 32) {
#pragma unroll
        for (int i = 0; i < 2; ++i) {
            float* d = &As[(lr + i * 32) * 36 + lk];
            float4 v = pa[i];
            d[0] = __uint_as_float(f2tf32(v.x));
            d[1] = __uint_as_float(f2tf32(v.y));
            d[2] = __uint_as_float(f2tf32(v.z));
            d[3] = __uint_as_float(f2tf32(v.w));
        }
#pragma unroll
        for (int i = 0; i < 4; ++i) {
            float* d = &Bs[(lr + i * 32) * 36 + lk];
            float4 v = pb[i];
            d[0] = __uint_as_float(f2tf32(v.x));
            d[1] = __uint_as_float(f2tf32(v.y));
            d[2] = __uint_as_float(f2tf32(v.z));
            d[3] = __uint_as_float(f2tf32(v.w));
        }
        __syncthreads();

        if (k0 + 32 < HH) {
            pa[0] = *(const float4*)(aptr + k0 + 32);
            pa[1] = *(const float4*)(aptr + (size_t)32 * ldh + k0 + 32);
#pragma unroll
            for (int i = 0; i < 4; ++i) pb[i] = *(const float4*)(bptr[i] + k0 + 32);
        }

#pragma unroll
        for (int kk = 0; kk < 4; ++kk) {
            uint32_t af[2][4], bf[4][2];
#pragma unroll
            for (int mt = 0; mt < 2; ++mt) {
                const float* s = &As[(wm * 32 + mt * 16 + qid) * 36 + kk * 8 + tig];
                af[mt][0] = __float_as_uint(s[0]);
                af[mt][1] = __float_as_uint(s[8 * 36]);
                af[mt][2] = __float_as_uint(s[4]);
                af[mt][3] = __float_as_uint(s[8 * 36 + 4]);
            }
#pragma unroll
            for (int nt = 0; nt < 4; ++nt) {
                const float* s = &Bs[(gate * 32 + nt * 8 + qid) * 36 + kk * 8 + tig];
                bf[nt][0] = __float_as_uint(s[0]);
                bf[nt][1] = __float_as_uint(s[4]);
            }
#pragma unroll
            for (int mt = 0; mt < 2; ++mt)
#pragma unroll
                for (int nt = 0; nt < 4; ++nt)
                    mma8(acc[mt][nt], af[mt][0], af[mt][1], af[mt][2], af[mt][3],
                         bf[nt][0], bf[nt][1]);
        }
        __syncthreads();
    }

    // ---- epilogue: gates + Gx -> smem Gt[4][64][33] ----
    float* Gt = smem;
#pragma unroll
    for (int mt = 0; mt < 2; ++mt) {
        const int rl = wm * 32 + mt * 16 + qid;      // 0..63 (row), +8 variant below
        const int bglob = m0 + rl;
        const float* gxr = Gx + ((size_t)bglob * LL + t) * G4 + gate * HH + u0;
#pragma unroll
        for (int nt = 0; nt < 4; ++nt) {
            const int cl = nt * 8 + 2 * tig;
            float2 g0 = *(const float2*)(gxr + cl);
            float2 g1 = *(const float2*)(gxr + (size_t)8 * LL * G4 + cl);
            float* d0 = &Gt[(gate * 64 + rl) * 33 + cl];
            float* d8 = &Gt[(gate * 64 + rl + 8) * 33 + cl];
            d0[0] = acc[mt][nt][0] + g0.x;
            d0[1] = acc[mt][nt][1] + g0.y;
            d8[0] = acc[mt][nt][2] + g1.x;
            d8[1] = acc[mt][nt][3] + g1.y;
        }
    }
    __syncthreads();

    // ---- LSTM cell on the 64x32 tile ----
    {
        const int r  = tid >> 2;           // 0..63
        const int cb = (tid & 3) * 8;      // 0,8,16,24
        const int bglob = m0 + r;
#pragma unroll
        for (int j = 0; j < 8; ++j) {
            const int u = cb + j;
            const float gi = Gt[(0 * 64 + r) * 33 + u];
            const float gf = Gt[(1 * 64 + r) * 33 + u];
            const float gg = Gt[(2 * 64 + r) * 33 + u];
            const float go = Gt[(3 * 64 + r) * 33 + u];
            const int ci = bglob * HH + u0 + u;
            const float c  = csrc[ci];
            const float si = 1.f / (1.f + expf(-gi));
            const float sf = 1.f / (1.f + expf(-gf));
            const float so = 1.f / (1.f + expf(-go));
            const float cn = sf * c + si * tanhf(gg);
            const float hn = so * tanhf(cn);
            g_c[ci] = cn;
            enc[(size_t)bglob * LL * HH + (size_t)t * HH + u0 + u] = hn;
        }
    }
}

// ============================================================
// Launch
// ============================================================
extern "C" void kernel_launch(void* const* d_in, const int* in_sizes, int n_in,
                              void* d_out, int out_size)
{
    (void)in_sizes; (void)n_in; (void)out_size;
    const float* x   = (const float*)d_in[0];
    const float* h0  = (const float*)d_in[1];
    const float* c0  = (const float*)d_in[2];
    const float* Wih = (const float*)d_in[3];
    const float* Whh = (const float*)d_in[4];
    const float* bih = (const float*)d_in[5];
    const float* bhh = (const float*)d_in[6];
    const float* Wa  = (const float*)d_in[7];
    // d_in[8] = ba: cancels inside softmax, never read.

    float* att = (float*)d_out;                       // (B, L, D)
    float* enc = att + (size_t)BB * LL * DD;          // (B, L, H)

    float *wi, *gx, *cbuf;
    cudaGetSymbolAddress((void**)&wi,   g_WI);
    cudaGetSymbolAddress((void**)&gx,   g_Gx);
    cudaGetSymbolAddress((void**)&cbuf, g_c);

    // 1) attention weights + att output + WI scratch
    attn_kernel<<<BB, DD>>>(x, Wa, att);

    // 2) big parallel input projection (tf32 tensor cores)
    {
        dim3 grid(G4 / 64, (BB * LL) / 128);          // (32, 128)
        gemm_xproj<<<grid, 256>>>(wi, Wih, bih, bhh, gx);
    }

    // 3) recurrence: fused gates GEMM + LSTM cell, one launch per step
    for (int t = 0; t < LL; ++t) {
        const float* hprev = (t == 0) ? h0 : (enc + (size_t)(t - 1) * HH);
        const int    ldh   = (t == 0) ? HH : LL * HH;
        const float* csrc  = (t == 0) ? c0 : cbuf;
        dim3 grid(HH / 32, BB / 64);                  // (16, 4)
        rec_step<<<grid, 256>>>(hprev, ldh, csrc, Whh, gx, enc, t);
    }
}

// round 4
// speedup vs baseline: 3.0838x; 1.6834x over previous
#include <cuda_runtime.h>
#include <math.h>
#include <stdint.h>

// Problem dims (fixed)
#define BB   256      // batch
#define LL   64       // seq len
#define DD   256      // input dim
#define HH   512      // hidden
#define G4   2048     // 4*H

#define NBLK 128      // persistent grid: 4 batch groups x 32 unit slices

// -------- scratch (device globals: allocation-free) --------
__device__ float g_WI[(size_t)BB * LL * DD];        // 16 MB
__device__ float g_Gx[(size_t)BB * LL * G4];        // 128 MB
__device__ float g_h[2 * BB * HH];                  // 1 MB ping-pong h (tf32-rounded)
__device__ unsigned g_bar_cnt = 0;
__device__ volatile unsigned g_bar_sense = 0;

// ---------- helpers ----------
__device__ __forceinline__ uint32_t f2tf32(float f) {
    uint32_t u;
    asm("cvt.rna.tf32.f32 %0, %1;" : "=r"(u) : "f"(f));
    return u;
}

__device__ __forceinline__ void mma8(float* c,
                                     uint32_t a0, uint32_t a1, uint32_t a2, uint32_t a3,
                                     uint32_t b0, uint32_t b1)
{
    asm volatile("mma.sync.aligned.m16n8k8.row.col.f32.tf32.tf32.f32 "
                 "{%0,%1,%2,%3},{%4,%5,%6,%7},{%8,%9},{%0,%1,%2,%3};"
                 : "+f"(c[0]), "+f"(c[1]), "+f"(c[2]), "+f"(c[3])
                 : "r"(a0), "r"(a1), "r"(a2), "r"(a3), "r"(b0), "r"(b1));
}

__device__ __forceinline__ void cpa16(void* dst, const void* src) {
    uint32_t d = (uint32_t)__cvta_generic_to_shared(dst);
    asm volatile("cp.async.cg.shared.global [%0], [%1], 16;" :: "r"(d), "l"(src));
}
#define CPA_COMMIT() asm volatile("cp.async.commit_group;")
#define CPA_WAIT(n)  asm volatile("cp.async.wait_group %0;" :: "n"(n))

// sense-reversing grid barrier (all NBLK blocks co-resident: 1 block/SM)
__device__ __forceinline__ void grid_barrier(unsigned& local_sense) {
    __syncthreads();
    if (threadIdx.x == 0) {
        unsigned my = local_sense ^ 1u;
        local_sense = my;
        __threadfence();                       // release our writes
        if (atomicAdd(&g_bar_cnt, 1u) == (unsigned)(gridDim.x - 1)) {
            atomicExch(&g_bar_cnt, 0u);
            __threadfence();                   // order reset before release
            g_bar_sense = my;
        } else {
            while (g_bar_sense != my) __nanosleep(32);
        }
        __threadfence();                       // acquire peers' writes
    }
    __syncthreads();
}

// ============================================================
// Kernel 1: a = softmax_d(x^T @ Wx); att = a (all t); WI = a*x
// (recurrent logit term is constant over softmax axis -> cancels)
// ============================================================
__global__ void attn_kernel(const float* __restrict__ x,
                            const float* __restrict__ Wa,
                            float* __restrict__ att)
{
    __shared__ float wx[LL];
    __shared__ float red[DD];
    const int b = blockIdx.x;
    const int d = threadIdx.x;

    if (d < LL) wx[d] = Wa[2 * HH + d];
    __syncthreads();

    const float* xb = x + (size_t)b * LL * DD;
    float ex = 0.f;
#pragma unroll
    for (int l = 0; l < LL; ++l)
        ex += xb[l * DD + d] * wx[l];

    red[d] = ex; __syncthreads();
    for (int s = DD / 2; s > 0; s >>= 1) {
        if (d < s) red[d] = fmaxf(red[d], red[d + s]);
        __syncthreads();
    }
    const float mx = red[0];
    __syncthreads();

    const float e = expf(ex - mx);
    red[d] = e; __syncthreads();
    for (int s = DD / 2; s > 0; s >>= 1) {
        if (d < s) red[d] += red[d + s];
        __syncthreads();
    }
    const float a = e / red[0];

    float* attb = att + (size_t)b * LL * DD;
    float* wib  = g_WI + (size_t)b * LL * DD;
#pragma unroll 4
    for (int t = 0; t < LL; ++t) {
        attb[t * DD + d] = a;
        wib[t * DD + d]  = a * xb[t * DD + d];
    }
}

// ============================================================
// Kernel 2: Gx = WI @ Wih^T + b_ih + b_hh   (16384 x 2048 x 256, tf32)
// ============================================================
__global__ __launch_bounds__(256) void gemm_xproj(
    const float* __restrict__ A,
    const float* __restrict__ Bw,
    const float* __restrict__ b1,
    const float* __restrict__ b2,
    float* __restrict__ C)
{
    __shared__ float As[128 * 36];
    __shared__ float Bs[64 * 36];

    const int tid  = threadIdx.x;
    const int lane = tid & 31, warp = tid >> 5;
    const int qid  = lane >> 2, tig = lane & 3;
    const int wm   = warp >> 1;
    const int wn   = warp & 1;
    const int m0   = blockIdx.y * 128;
    const int n0   = blockIdx.x * 64;

    const int lr = tid >> 3;
    const int lk = (tid & 7) * 4;

    const float* aptr = A  + (size_t)(m0 + lr) * DD + lk;
    const float* bptr = Bw + (size_t)(n0 + lr) * DD + lk;

    float4 pa[4], pb[2];
#pragma unroll
    for (int i = 0; i < 4; ++i) pa[i] = *(const float4*)(aptr + (size_t)i * 32 * DD);
#pragma unroll
    for (int i = 0; i < 2; ++i) pb[i] = *(const float4*)(bptr + (size_t)i * 32 * DD);

    float acc[2][4][4] = {};

    for (int k0 = 0; k0 < DD; k0 += 32) {
#pragma unroll
        for (int i = 0; i < 4; ++i) {
            float* d = &As[(lr + i * 32) * 36 + lk];
            d[0] = __uint_as_float(f2tf32(pa[i].x));
            d[1] = __uint_as_float(f2tf32(pa[i].y));
            d[2] = __uint_as_float(f2tf32(pa[i].z));
            d[3] = __uint_as_float(f2tf32(pa[i].w));
        }
#pragma unroll
        for (int i = 0; i < 2; ++i) {
            float* d = &Bs[(lr + i * 32) * 36 + lk];
            d[0] = __uint_as_float(f2tf32(pb[i].x));
            d[1] = __uint_as_float(f2tf32(pb[i].y));
            d[2] = __uint_as_float(f2tf32(pb[i].z));
            d[3] = __uint_as_float(f2tf32(pb[i].w));
        }
        __syncthreads();

        if (k0 + 32 < DD) {
#pragma unroll
            for (int i = 0; i < 4; ++i) pa[i] = *(const float4*)(aptr + k0 + 32 + (size_t)i * 32 * DD);
#pragma unroll
            for (int i = 0; i < 2; ++i) pb[i] = *(const float4*)(bptr + k0 + 32 + (size_t)i * 32 * DD);
        }

#pragma unroll
        for (int kk = 0; kk < 4; ++kk) {
            uint32_t af[2][4], bf[4][2];
#pragma unroll
            for (int mt = 0; mt < 2; ++mt) {
                const float* s = &As[(wm * 32 + mt * 16 + qid) * 36 + kk * 8 + tig];
                af[mt][0] = __float_as_uint(s[0]);
                af[mt][1] = __float_as_uint(s[8 * 36]);
                af[mt][2] = __float_as_uint(s[4]);
                af[mt][3] = __float_as_uint(s[8 * 36 + 4]);
            }
#pragma unroll
            for (int nt = 0; nt < 4; ++nt) {
                const float* s = &Bs[(wn * 32 + nt * 8 + qid) * 36 + kk * 8 + tig];
                bf[nt][0] = __float_as_uint(s[0]);
                bf[nt][1] = __float_as_uint(s[4]);
            }
#pragma unroll
            for (int mt = 0; mt < 2; ++mt)
#pragma unroll
                for (int nt = 0; nt < 4; ++nt)
                    mma8(acc[mt][nt], af[mt][0], af[mt][1], af[mt][2], af[mt][3],
                         bf[nt][0], bf[nt][1]);
        }
        __syncthreads();
    }

#pragma unroll
    for (int mt = 0; mt < 2; ++mt) {
        const int m = m0 + wm * 32 + mt * 16 + qid;
#pragma unroll
        for (int nt = 0; nt < 4; ++nt) {
            const int n = n0 + wn * 32 + nt * 8 + 2 * tig;
            const float bb0 = b1[n] + b2[n];
            const float bb1 = b1[n + 1] + b2[n + 1];
            float2 o0 = {acc[mt][nt][0] + bb0, acc[mt][nt][1] + bb1};
            float2 o1 = {acc[mt][nt][2] + bb0, acc[mt][nt][3] + bb1};
            *(float2*)(C + (size_t)m * G4 + n)       = o0;
            *(float2*)(C + (size_t)(m + 8) * G4 + n) = o1;
        }
    }
}

// ============================================================
// Kernel 3: PERSISTENT recurrence. 128 blocks = 4 batch groups x 32
// unit slices. Whh slice lives in smem for all 64 steps; c in regs;
// h ping-pongs in gmem (tf32-rounded); grid barrier between steps.
// ============================================================
#define WHH_F  (64 * 516)                 // Whh slice, tf32 in smem
#define HS_F   (64 * 68)                  // one h-chunk buffer
#define GXS_F  (64 * 68)                  // Gx tile buffer
#define SMEM_REC ((WHH_F + 2 * HS_F + GXS_F) * 4)   // 184320 B

__global__ void __launch_bounds__(256, 1) rec_persistent(
    const float* __restrict__ h0,
    const float* __restrict__ c0,
    const float* __restrict__ Whh,
    const float* __restrict__ Gx,
    float* __restrict__ enc,
    float* __restrict__ hbuf)
{
    extern __shared__ float sm[];
    float* WhhS = sm;                      // [64][516]
    float* hS   = sm + WHH_F;              // [2][64][68]
    float* GxS  = hS + 2 * HS_F;           // [64][68]
    float* Gt   = hS;                      // epilogue reuse (64*68)

    const int tid  = threadIdx.x;
    const int lane = tid & 31, warp = tid >> 5;
    const int qid  = lane >> 2, tig = lane & 3;
    const int wm   = warp >> 2;            // 0..1 : batch half
    const int wg   = warp & 3;             // 0..3 : gate
    const int bid  = blockIdx.x;
    const int m0   = (bid >> 5) * 64;      // batch group base
    const int u0   = (bid & 31) * 16;      // unit slice base

    // ---- load Whh slice to smem (once), tf32-rounded ----
    for (int idx = tid; idx < 64 * 512; idx += 256) {
        const int r = idx >> 9, k = idx & 511;
        const int gate = r >> 4, uu = r & 15;
        const float v = Whh[(size_t)(gate * HH + u0 + uu) * HH + k];
        WhhS[r * 516 + k] = __uint_as_float(f2tf32(v));
    }

    // ---- init h(0) slice in ping buffer 0 (tf32-rounded) ----
    for (int idx = tid; idx < 64 * 16; idx += 256) {
        const int b = idx >> 4, uu = idx & 15;
        const float v = h0[(size_t)(m0 + b) * HH + u0 + uu];
        hbuf[(size_t)(m0 + b) * HH + u0 + uu] = __uint_as_float(f2tf32(v));
    }

    // ---- c slice in registers ----
    const int cr = tid >> 2;               // 0..63 (batch rel)
    const int cu = (tid & 3) * 4;          // 0,4,8,12 (unit rel)
    float creg[4];
#pragma unroll
    for (int k = 0; k < 4; ++k)
        creg[k] = c0[(size_t)(m0 + cr) * HH + u0 + cu + k];

    unsigned local_sense = 0;

    for (int t = 0; t < LL; ++t) {
        const float* hsrc = hbuf + (size_t)(t & 1) * BB * HH;
        float*       hdst = hbuf + (size_t)((t + 1) & 1) * BB * HH;

        // prefetch Gx tile for this step (static input; ok pre-barrier)
        {
            const float* gbase = Gx + (size_t)m0 * LL * G4 + (size_t)t * G4 + u0;
#pragma unroll
            for (int i = 0; i < 4; ++i) {
                const int idx = tid + i * 256;
                const int b = idx >> 4, gate = (idx >> 2) & 3, q = idx & 3;
                cpa16(&GxS[b * 68 + gate * 16 + q * 4],
                      gbase + (size_t)b * LL * G4 + gate * HH + q * 4);
            }
            CPA_COMMIT();
        }

        grid_barrier(local_sense);   // h(t) visible from all peers

        // chunk 0 of h
        {
#pragma unroll
            for (int i = 0; i < 4; ++i) {
                const int idx = tid + i * 256;
                const int r = idx >> 4, q = idx & 15;
                cpa16(&hS[r * 68 + q * 4],
                      hsrc + (size_t)(m0 + r) * HH + q * 4);
            }
            CPA_COMMIT();
        }

        float acc[2][2][4] = {};

#pragma unroll
        for (int kc = 0; kc < 8; ++kc) {
            if (kc < 7) {
                const int k0 = (kc + 1) * 64, buf = (kc + 1) & 1;
#pragma unroll
                for (int i = 0; i < 4; ++i) {
                    const int idx = tid + i * 256;
                    const int r = idx >> 4, q = idx & 15;
                    cpa16(&hS[buf * HS_F + r * 68 + q * 4],
                          hsrc + (size_t)(m0 + r) * HH + k0 + q * 4);
                }
                CPA_COMMIT();
                CPA_WAIT(1);
            } else {
                CPA_WAIT(0);   // also drains Gx group
            }
            __syncthreads();

            const float* hb = &hS[(kc & 1) * HS_F];
            const float* wb = &WhhS[kc * 64];
#pragma unroll
            for (int kk = 0; kk < 8; ++kk) {
                uint32_t af[2][4], bf[2][2];
#pragma unroll
                for (int mt = 0; mt < 2; ++mt) {
                    const float* s = hb + (wm * 32 + mt * 16 + qid) * 68 + kk * 8 + tig;
                    af[mt][0] = __float_as_uint(s[0]);
                    af[mt][1] = __float_as_uint(s[8 * 68]);
                    af[mt][2] = __float_as_uint(s[4]);
                    af[mt][3] = __float_as_uint(s[8 * 68 + 4]);
                }
#pragma unroll
                for (int nt = 0; nt < 2; ++nt) {
                    const float* s = wb + (wg * 16 + nt * 8 + qid) * 516 + kk * 8 + tig;
                    bf[nt][0] = __float_as_uint(s[0]);
                    bf[nt][1] = __float_as_uint(s[4]);
                }
#pragma unroll
                for (int mt = 0; mt < 2; ++mt)
#pragma unroll
                    for (int nt = 0; nt < 2; ++nt)
                        mma8(acc[mt][nt], af[mt][0], af[mt][1], af[mt][2], af[mt][3],
                             bf[nt][0], bf[nt][1]);
            }
            __syncthreads();
        }

        // ---- epilogue: Gt = acc + Gx (exchange gates via smem) ----
#pragma unroll
        for (int mt = 0; mt < 2; ++mt) {
            const int rl = wm * 32 + mt * 16 + qid;
#pragma unroll
            for (int nt = 0; nt < 2; ++nt) {
                const int cl = wg * 16 + nt * 8 + 2 * tig;
                const float2 gx0 = *(const float2*)&GxS[rl * 68 + cl];
                const float2 gx1 = *(const float2*)&GxS[(rl + 8) * 68 + cl];
                float2 o0 = {acc[mt][nt][0] + gx0.x, acc[mt][nt][1] + gx0.y};
                float2 o1 = {acc[mt][nt][2] + gx1.x, acc[mt][nt][3] + gx1.y};
                *(float2*)&Gt[rl * 68 + cl]       = o0;
                *(float2*)&Gt[(rl + 8) * 68 + cl] = o1;
            }
        }
        __syncthreads();

        // ---- LSTM cell: c in regs; write enc (exact) + h (tf32) ----
        {
            const float4 gi = *(const float4*)&Gt[cr * 68 +  0 + cu];
            const float4 gf = *(const float4*)&Gt[cr * 68 + 16 + cu];
            const float4 gg = *(const float4*)&Gt[cr * 68 + 32 + cu];
            const float4 go = *(const float4*)&Gt[cr * 68 + 48 + cu];
            const float gia[4] = {gi.x, gi.y, gi.z, gi.w};
            const float gfa[4] = {gf.x, gf.y, gf.z, gf.w};
            const float gga[4] = {gg.x, gg.y, gg.z, gg.w};
            const float goa[4] = {go.x, go.y, go.z, go.w};

            float4 ho, hr;
            float* hop = &ho.x;
            float* hrp = &hr.x;
#pragma unroll
            for (int k = 0; k < 4; ++k) {
                const float si = 1.f / (1.f + expf(-gia[k]));
                const float sf = 1.f / (1.f + expf(-gfa[k]));
                const float so = 1.f / (1.f + expf(-goa[k]));
                const float cn = sf * creg[k] + si * tanhf(gga[k]);
                const float hn = so * tanhf(cn);
                creg[k] = cn;
                hop[k] = hn;
                hrp[k] = __uint_as_float(f2tf32(hn));
            }
            *(float4*)(enc + (size_t)(m0 + cr) * LL * HH + (size_t)t * HH + u0 + cu) = ho;
            *(float4*)(hdst + (size_t)(m0 + cr) * HH + u0 + cu) = hr;
        }
        // next grid_barrier (loop top) publishes hdst
    }
}

// ============================================================
// Launch
// ============================================================
extern "C" void kernel_launch(void* const* d_in, const int* in_sizes, int n_in,
                              void* d_out, int out_size)
{
    (void)in_sizes; (void)n_in; (void)out_size;
    const float* x   = (const float*)d_in[0];
    const float* h0  = (const float*)d_in[1];
    const float* c0  = (const float*)d_in[2];
    const float* Wih = (const float*)d_in[3];
    const float* Whh = (const float*)d_in[4];
    const float* bih = (const float*)d_in[5];
    const float* bhh = (const float*)d_in[6];
    const float* Wa  = (const float*)d_in[7];
    // d_in[8] = ba: cancels inside softmax, never read.

    float* att = (float*)d_out;                       // (B, L, D)
    float* enc = att + (size_t)BB * LL * DD;          // (B, L, H)

    float *wi, *gx, *hbuf;
    cudaGetSymbolAddress((void**)&wi,   g_WI);
    cudaGetSymbolAddress((void**)&gx,   g_Gx);
    cudaGetSymbolAddress((void**)&hbuf, g_h);

    static int smem_set = 0;
    if (!smem_set) {
        cudaFuncSetAttribute(rec_persistent,
                             cudaFuncAttributeMaxDynamicSharedMemorySize, SMEM_REC);
        smem_set = 1;
    }

    // 1) attention weights + att output + WI scratch
    attn_kernel<<<BB, DD>>>(x, Wa, att);

    // 2) big parallel input projection (tf32 tensor cores)
    {
        dim3 grid(G4 / 64, (BB * LL) / 128);
        gemm_xproj<<<grid, 256>>>(wi, Wih, bih, bhh, gx);
    }

    // 3) whole recurrence in ONE persistent kernel
    rec_persistent<<<NBLK, 256, SMEM_REC>>>(h0, c0, Whh, gx, enc, hbuf);
}

// round 5
// speedup vs baseline: 3.4776x; 1.1277x over previous
#include <cuda_runtime.h>
#include <math.h>
#include <stdint.h>

// Problem dims (fixed)
#define BB   256      // batch
#define LL   64       // seq len
#define DD   256      // input dim
#define HH   512      // hidden
#define G4   2048     // 4*H

#define NBLK 128      // persistent grid: 4 batch groups x 32 unit slices
#define NGRP 4        // independent barrier domains (32 blocks each)

// -------- scratch (device globals: allocation-free) --------
__device__ float g_WI[(size_t)BB * LL * DD];        // 16 MB
__device__ float g_Gx[(size_t)BB * LL * G4];        // 128 MB
__device__ float g_h[2 * BB * HH];                  // 1 MB ping-pong h (tf32-rounded)
__device__ unsigned g_ctr[NGRP][LL];                // per-group per-step arrival counters

// ---------- helpers ----------
__device__ __forceinline__ uint32_t f2tf32(float f) {
    uint32_t u;
    asm("cvt.rna.tf32.f32 %0, %1;" : "=r"(u) : "f"(f));
    return u;
}

__device__ __forceinline__ void mma8(float* c,
                                     uint32_t a0, uint32_t a1, uint32_t a2, uint32_t a3,
                                     uint32_t b0, uint32_t b1)
{
    asm volatile("mma.sync.aligned.m16n8k8.row.col.f32.tf32.tf32.f32 "
                 "{%0,%1,%2,%3},{%4,%5,%6,%7},{%8,%9},{%0,%1,%2,%3};"
                 : "+f"(c[0]), "+f"(c[1]), "+f"(c[2]), "+f"(c[3])
                 : "r"(a0), "r"(a1), "r"(a2), "r"(a3), "r"(b0), "r"(b1));
}

__device__ __forceinline__ void cpa16(void* dst, const void* src) {
    uint32_t d = (uint32_t)__cvta_generic_to_shared(dst);
    asm volatile("cp.async.cg.shared.global [%0], [%1], 16;" :: "r"(d), "l"(src));
}
#define CPA_COMMIT() asm volatile("cp.async.commit_group;")
#define CPA_WAIT(n)  asm volatile("cp.async.wait_group %0;" :: "n"(n))

__device__ __forceinline__ void bar_arrive(unsigned* p) {
    asm volatile("red.release.gpu.global.add.u32 [%0], 1;" :: "l"(p) : "memory");
}
__device__ __forceinline__ unsigned ld_acq(const unsigned* p) {
    unsigned v;
    asm volatile("ld.acquire.gpu.global.u32 %0, [%1];" : "=r"(v) : "l"(p) : "memory");
    return v;
}

// ============================================================
// Kernel 1: a = softmax_d(x^T @ Wx); att = a (all t); WI = a*x
// (recurrent logit term is constant over softmax axis -> cancels)
// ============================================================
__global__ void attn_kernel(const float* __restrict__ x,
                            const float* __restrict__ Wa,
                            float* __restrict__ att)
{
    __shared__ float wx[LL];
    __shared__ float red[DD];
    const int b = blockIdx.x;
    const int d = threadIdx.x;

    if (d < LL) wx[d] = Wa[2 * HH + d];
    __syncthreads();

    const float* xb = x + (size_t)b * LL * DD;
    float ex = 0.f;
#pragma unroll
    for (int l = 0; l < LL; ++l)
        ex += xb[l * DD + d] * wx[l];

    red[d] = ex; __syncthreads();
    for (int s = DD / 2; s > 0; s >>= 1) {
        if (d < s) red[d] = fmaxf(red[d], red[d + s]);
        __syncthreads();
    }
    const float mx = red[0];
    __syncthreads();

    const float e = expf(ex - mx);
    red[d] = e; __syncthreads();
    for (int s = DD / 2; s > 0; s >>= 1) {
        if (d < s) red[d] += red[d + s];
        __syncthreads();
    }
    const float a = e / red[0];

    float* attb = att + (size_t)b * LL * DD;
    float* wib  = g_WI + (size_t)b * LL * DD;
#pragma unroll 4
    for (int t = 0; t < LL; ++t) {
        attb[t * DD + d] = a;
        wib[t * DD + d]  = a * xb[t * DD + d];
    }
}

// ============================================================
// Kernel 2: Gx = WI @ Wih^T + b_ih + b_hh   (16384 x 2048 x 256, tf32)
// ============================================================
__global__ __launch_bounds__(256) void gemm_xproj(
    const float* __restrict__ A,
    const float* __restrict__ Bw,
    const float* __restrict__ b1,
    const float* __restrict__ b2,
    float* __restrict__ C)
{
    __shared__ float As[128 * 36];
    __shared__ float Bs[64 * 36];

    const int tid  = threadIdx.x;
    const int lane = tid & 31, warp = tid >> 5;
    const int qid  = lane >> 2, tig = lane & 3;
    const int wm   = warp >> 1;
    const int wn   = warp & 1;
    const int m0   = blockIdx.y * 128;
    const int n0   = blockIdx.x * 64;

    const int lr = tid >> 3;
    const int lk = (tid & 7) * 4;

    const float* aptr = A  + (size_t)(m0 + lr) * DD + lk;
    const float* bptr = Bw + (size_t)(n0 + lr) * DD + lk;

    float4 pa[4], pb[2];
#pragma unroll
    for (int i = 0; i < 4; ++i) pa[i] = *(const float4*)(aptr + (size_t)i * 32 * DD);
#pragma unroll
    for (int i = 0; i < 2; ++i) pb[i] = *(const float4*)(bptr + (size_t)i * 32 * DD);

    float acc[2][4][4] = {};

    for (int k0 = 0; k0 < DD; k0 += 32) {
#pragma unroll
        for (int i = 0; i < 4; ++i) {
            float* d = &As[(lr + i * 32) * 36 + lk];
            d[0] = __uint_as_float(f2tf32(pa[i].x));
            d[1] = __uint_as_float(f2tf32(pa[i].y));
            d[2] = __uint_as_float(f2tf32(pa[i].z));
            d[3] = __uint_as_float(f2tf32(pa[i].w));
        }
#pragma unroll
        for (int i = 0; i < 2; ++i) {
            float* d = &Bs[(lr + i * 32) * 36 + lk];
            d[0] = __uint_as_float(f2tf32(pb[i].x));
            d[1] = __uint_as_float(f2tf32(pb[i].y));
            d[2] = __uint_as_float(f2tf32(pb[i].z));
            d[3] = __uint_as_float(f2tf32(pb[i].w));
        }
        __syncthreads();

        if (k0 + 32 < DD) {
#pragma unroll
            for (int i = 0; i < 4; ++i) pa[i] = *(const float4*)(aptr + k0 + 32 + (size_t)i * 32 * DD);
#pragma unroll
            for (int i = 0; i < 2; ++i) pb[i] = *(const float4*)(bptr + k0 + 32 + (size_t)i * 32 * DD);
        }

#pragma unroll
        for (int kk = 0; kk < 4; ++kk) {
            uint32_t af[2][4], bf[4][2];
#pragma unroll
            for (int mt = 0; mt < 2; ++mt) {
                const float* s = &As[(wm * 32 + mt * 16 + qid) * 36 + kk * 8 + tig];
                af[mt][0] = __float_as_uint(s[0]);
                af[mt][1] = __float_as_uint(s[8 * 36]);
                af[mt][2] = __float_as_uint(s[4]);
                af[mt][3] = __float_as_uint(s[8 * 36 + 4]);
            }
#pragma unroll
            for (int nt = 0; nt < 4; ++nt) {
                const float* s = &Bs[(wn * 32 + nt * 8 + qid) * 36 + kk * 8 + tig];
                bf[nt][0] = __float_as_uint(s[0]);
                bf[nt][1] = __float_as_uint(s[4]);
            }
#pragma unroll
            for (int mt = 0; mt < 2; ++mt)
#pragma unroll
                for (int nt = 0; nt < 4; ++nt)
                    mma8(acc[mt][nt], af[mt][0], af[mt][1], af[mt][2], af[mt][3],
                         bf[nt][0], bf[nt][1]);
        }
        __syncthreads();
    }

#pragma unroll
    for (int mt = 0; mt < 2; ++mt) {
        const int m = m0 + wm * 32 + mt * 16 + qid;
#pragma unroll
        for (int nt = 0; nt < 4; ++nt) {
            const int n = n0 + wn * 32 + nt * 8 + 2 * tig;
            const float bb0 = b1[n] + b2[n];
            const float bb1 = b1[n + 1] + b2[n + 1];
            float2 o0 = {acc[mt][nt][0] + bb0, acc[mt][nt][1] + bb1};
            float2 o1 = {acc[mt][nt][2] + bb0, acc[mt][nt][3] + bb1};
            *(float2*)(C + (size_t)m * G4 + n)       = o0;
            *(float2*)(C + (size_t)(m + 8) * G4 + n) = o1;
        }
    }
}

// ============================================================
// Kernel 3: PERSISTENT recurrence. 128 blocks = 4 batch groups x 32
// unit slices. Per-GROUP monotonic barriers (32 blocks each, counters
// pre-zeroed by a memset node). Whh slice resident in smem; c in regs;
// h ping-pongs in gmem (tf32); 4-buffer cp.async pipeline, 1 sync/chunk.
// ============================================================
#define WHH_F  (64 * 516)                 // Whh slice, tf32 in smem
#define HCH_F  (64 * 68)                  // one 64-wide K chunk of h
#define GXS_F  (64 * 68)                  // Gx tile buffer
#define SMEM_REC ((WHH_F + 4 * HCH_F + GXS_F) * 4)   // 219136 B

__global__ void __launch_bounds__(256, 1) rec_persistent(
    const float* __restrict__ h0,
    const float* __restrict__ c0,
    const float* __restrict__ Whh,
    const float* __restrict__ Gx,
    float* __restrict__ enc,
    float* __restrict__ hbuf)
{
    extern __shared__ float sm[];
    float* WhhS = sm;                      // [64][516]
    float* hS   = sm + WHH_F;              // [4][64][68]
    float* GxS  = hS + 4 * HCH_F;          // [64][68]
    float* Gt   = hS;                      // epilogue reuse (buf 0)

    const int tid  = threadIdx.x;
    const int lane = tid & 31, warp = tid >> 5;
    const int qid  = lane >> 2, tig = lane & 3;
    const int wm   = warp >> 2;            // 0..1 : batch half
    const int wg   = warp & 3;             // 0..3 : gate
    const int bid  = blockIdx.x;
    const int grp  = bid >> 5;             // batch group 0..3
    const int m0   = grp * 64;             // batch group base
    const int u0   = (bid & 31) * 16;      // unit slice base

    // ---- load Whh slice to smem (once), tf32-rounded ----
    for (int idx = tid; idx < 64 * 512; idx += 256) {
        const int r = idx >> 9, k = idx & 511;
        const int gate = r >> 4, uu = r & 15;
        const float v = Whh[(size_t)(gate * HH + u0 + uu) * HH + k];
        WhhS[r * 516 + k] = __uint_as_float(f2tf32(v));
    }

    // ---- init h(0) slice in ping buffer 0 (tf32-rounded) ----
    for (int idx = tid; idx < 64 * 16; idx += 256) {
        const int b = idx >> 4, uu = idx & 15;
        const float v = h0[(size_t)(m0 + b) * HH + u0 + uu];
        hbuf[(size_t)(m0 + b) * HH + u0 + uu] = __uint_as_float(f2tf32(v));
    }

    // ---- c slice in registers ----
    const int cr = tid >> 2;               // 0..63 (batch rel)
    const int cu = (tid & 3) * 4;          // 0,4,8,12 (unit rel)
    float creg[4];
#pragma unroll
    for (int k = 0; k < 4; ++k)
        creg[k] = c0[(size_t)(m0 + cr) * HH + u0 + cu + k];

    for (int t = 0; t < LL; ++t) {
        const float* hsrc = hbuf + (size_t)(t & 1) * BB * HH;
        float*       hdst = hbuf + (size_t)((t + 1) & 1) * BB * HH;

        // Gx prefetch for this step (static input; pre-barrier) -> group 0
        {
            const float* gbase = Gx + (size_t)m0 * LL * G4 + (size_t)t * G4 + u0;
#pragma unroll
            for (int i = 0; i < 4; ++i) {
                const int idx = tid + i * 256;
                const int b = idx >> 4, gate = (idx >> 2) & 3, q = idx & 3;
                cpa16(&GxS[b * 68 + gate * 16 + q * 4],
                      gbase + (size_t)b * LL * G4 + gate * HH + q * 4);
            }
            CPA_COMMIT();
        }

        // ---- per-group barrier: h(t) from the 32 peer blocks ----
        __syncthreads();                      // our hdst stores of t-1 done
        if (tid == 0) {
            unsigned* ctr = &g_ctr[grp][t];
            bar_arrive(ctr);
            while (ld_acq(ctr) < 32u) __nanosleep(32);
        }
        __syncthreads();

        // ---- issue h chunks 0..2 (buffers 0..2) ----
#pragma unroll
        for (int p = 0; p < 3; ++p) {
#pragma unroll
            for (int i = 0; i < 4; ++i) {
                const int idx = tid + i * 256;
                const int r = idx >> 4, q = idx & 15;
                cpa16(&hS[p * HCH_F + r * 68 + q * 4],
                      hsrc + (size_t)(m0 + r) * HH + p * 64 + q * 4);
            }
            CPA_COMMIT();
        }

        float acc[2][2][4] = {};

#pragma unroll
        for (int kc = 0; kc < 8; ++kc) {
            if (kc < 6)      { CPA_WAIT(2); }
            else if (kc == 6){ CPA_WAIT(1); }
            else             { CPA_WAIT(0); }
            __syncthreads();                   // chunk kc ready; buf (kc+3)&3 free

            if (kc < 5) {                      // issue chunk kc+3
                const int k0 = (kc + 3) * 64;
                float* hb3 = &hS[((kc + 3) & 3) * HCH_F];
#pragma unroll
                for (int i = 0; i < 4; ++i) {
                    const int idx = tid + i * 256;
                    const int r = idx >> 4, q = idx & 15;
                    cpa16(&hb3[r * 68 + q * 4],
                          hsrc + (size_t)(m0 + r) * HH + k0 + q * 4);
                }
                CPA_COMMIT();
            }

            const float* hb = &hS[(kc & 3) * HCH_F];
            const float* wb = &WhhS[kc * 64];
#pragma unroll
            for (int kk = 0; kk < 8; ++kk) {
                uint32_t af[2][4], bf[2][2];
#pragma unroll
                for (int mt = 0; mt < 2; ++mt) {
                    const float* s = hb + (wm * 32 + mt * 16 + qid) * 68 + kk * 8 + tig;
                    af[mt][0] = __float_as_uint(s[0]);
                    af[mt][1] = __float_as_uint(s[8 * 68]);
                    af[mt][2] = __float_as_uint(s[4]);
                    af[mt][3] = __float_as_uint(s[8 * 68 + 4]);
                }
#pragma unroll
                for (int nt = 0; nt < 2; ++nt) {
                    const float* s = wb + (wg * 16 + nt * 8 + qid) * 516 + kk * 8 + tig;
                    bf[nt][0] = __float_as_uint(s[0]);
                    bf[nt][1] = __float_as_uint(s[4]);
                }
#pragma unroll
                for (int mt = 0; mt < 2; ++mt)
#pragma unroll
                    for (int nt = 0; nt < 2; ++nt)
                        mma8(acc[mt][nt], af[mt][0], af[mt][1], af[mt][2], af[mt][3],
                             bf[nt][0], bf[nt][1]);
            }
            // no trailing sync: next iter's syncthreads covers buffer reuse
        }

        // ---- epilogue: Gt(=buf0) = acc + Gx; buf0 idle since kc=4 ----
#pragma unroll
        for (int mt = 0; mt < 2; ++mt) {
            const int rl = wm * 32 + mt * 16 + qid;
#pragma unroll
            for (int nt = 0; nt < 2; ++nt) {
                const int cl = wg * 16 + nt * 8 + 2 * tig;
                const float2 gx0 = *(const float2*)&GxS[rl * 68 + cl];
                const float2 gx1 = *(const float2*)&GxS[(rl + 8) * 68 + cl];
                float2 o0 = {acc[mt][nt][0] + gx0.x, acc[mt][nt][1] + gx0.y};
                float2 o1 = {acc[mt][nt][2] + gx1.x, acc[mt][nt][3] + gx1.y};
                *(float2*)&Gt[rl * 68 + cl]       = o0;
                *(float2*)&Gt[(rl + 8) * 68 + cl] = o1;
            }
        }
        __syncthreads();

        // ---- LSTM cell: c in regs; write enc (exact) + h (tf32) ----
        {
            const float4 gi = *(const float4*)&Gt[cr * 68 +  0 + cu];
            const float4 gf = *(const float4*)&Gt[cr * 68 + 16 + cu];
            const float4 gg = *(const float4*)&Gt[cr * 68 + 32 + cu];
            const float4 go = *(const float4*)&Gt[cr * 68 + 48 + cu];
            const float gia[4] = {gi.x, gi.y, gi.z, gi.w};
            const float gfa[4] = {gf.x, gf.y, gf.z, gf.w};
            const float gga[4] = {gg.x, gg.y, gg.z, gg.w};
            const float goa[4] = {go.x, go.y, go.z, go.w};

            float4 ho, hr;
            float* hop = &ho.x;
            float* hrp = &hr.x;
#pragma unroll
            for (int k = 0; k < 4; ++k) {
                const float si = 1.f / (1.f + expf(-gia[k]));
                const float sf = 1.f / (1.f + expf(-gfa[k]));
                const float so = 1.f / (1.f + expf(-goa[k]));
                const float cn = sf * creg[k] + si * tanhf(gga[k]);
                const float hn = so * tanhf(cn);
                creg[k] = cn;
                hop[k] = hn;
                hrp[k] = __uint_as_float(f2tf32(hn));
            }
            *(float4*)(enc + (size_t)(m0 + cr) * LL * HH + (size_t)t * HH + u0 + cu) = ho;
            *(float4*)(hdst + (size_t)(m0 + cr) * HH + u0 + cu) = hr;
        }
        // next step's barrier publishes hdst (release-arrive after syncthreads)
    }
}

// ============================================================
// Launch
// ============================================================
extern "C" void kernel_launch(void* const* d_in, const int* in_sizes, int n_in,
                              void* d_out, int out_size)
{
    (void)in_sizes; (void)n_in; (void)out_size;
    const float* x   = (const float*)d_in[0];
    const float* h0  = (const float*)d_in[1];
    const float* c0  = (const float*)d_in[2];
    const float* Wih = (const float*)d_in[3];
    const float* Whh = (const float*)d_in[4];
    const float* bih = (const float*)d_in[5];
    const float* bhh = (const float*)d_in[6];
    const float* Wa  = (const float*)d_in[7];
    // d_in[8] = ba: cancels inside softmax, never read.

    float* att = (float*)d_out;                       // (B, L, D)
    float* enc = att + (size_t)BB * LL * DD;          // (B, L, H)

    float *wi, *gx, *hbuf;
    void* ctr;
    cudaGetSymbolAddress((void**)&wi,   g_WI);
    cudaGetSymbolAddress((void**)&gx,   g_Gx);
    cudaGetSymbolAddress((void**)&hbuf, g_h);
    cudaGetSymbolAddress(&ctr,          g_ctr);

    static int smem_set = 0;
    if (!smem_set) {
        cudaFuncSetAttribute(rec_persistent,
                             cudaFuncAttributeMaxDynamicSharedMemorySize, SMEM_REC);
        smem_set = 1;
    }

    // 0) zero the per-step barrier counters (captured as a memset node)
    cudaMemsetAsync(ctr, 0, sizeof(unsigned) * NGRP * LL);

    // 1) attention weights + att output + WI scratch
    attn_kernel<<<BB, DD>>>(x, Wa, att);

    // 2) big parallel input projection (tf32 tensor cores)
    {
        dim3 grid(G4 / 64, (BB * LL) / 128);
        gemm_xproj<<<grid, 256>>>(wi, Wih, bih, bhh, gx);
    }

    // 3) whole recurrence in ONE persistent kernel
    rec_persistent<<<NBLK, 256, SMEM_REC>>>(h0, c0, Whh, gx, enc, hbuf);
}

// round 6
// speedup vs baseline: 4.7472x; 1.3651x over previous
#include <cuda_runtime.h>
#include <cuda_fp16.h>
#include <math.h>
#include <stdint.h>

// Problem dims (fixed)
#define BB   256      // batch
#define LL   64       // seq len
#define DD   256      // input dim
#define HH   512      // hidden
#define G4   2048     // 4*H

#define NBLK 128      // persistent grid: 8 batch groups x 16 unit slices
#define NGRP 8        // barrier domains (16 blocks each)
#define MB   32       // batch rows per block
#define UB   32       // units per block (x4 gates = 128 gate-cols)

// -------- scratch (device globals: allocation-free) --------
__device__ float  g_WI[(size_t)BB * LL * DD];     // 16 MB
__device__ float  g_Gx[(size_t)BB * LL * G4];     // 128 MB
__device__ __half g_h[2 * BB * HH];               // 0.5 MB ping-pong h (fp16)
__device__ unsigned g_ctr[NGRP][LL];              // per-group per-step arrival counters

// ---------- helpers ----------
__device__ __forceinline__ uint32_t f2tf32(float f) {
    uint32_t u;
    asm("cvt.rna.tf32.f32 %0, %1;" : "=r"(u) : "f"(f));
    return u;
}

__device__ __forceinline__ void mma8(float* c,
                                     uint32_t a0, uint32_t a1, uint32_t a2, uint32_t a3,
                                     uint32_t b0, uint32_t b1)
{
    asm volatile("mma.sync.aligned.m16n8k8.row.col.f32.tf32.tf32.f32 "
                 "{%0,%1,%2,%3},{%4,%5,%6,%7},{%8,%9},{%0,%1,%2,%3};"
                 : "+f"(c[0]), "+f"(c[1]), "+f"(c[2]), "+f"(c[3])
                 : "r"(a0), "r"(a1), "r"(a2), "r"(a3), "r"(b0), "r"(b1));
}

__device__ __forceinline__ void mma16(float* c,
                                      uint32_t a0, uint32_t a1, uint32_t a2, uint32_t a3,
                                      uint32_t b0, uint32_t b1)
{
    asm volatile("mma.sync.aligned.m16n8k16.row.col.f32.f16.f16.f32 "
                 "{%0,%1,%2,%3},{%4,%5,%6,%7},{%8,%9},{%0,%1,%2,%3};"
                 : "+f"(c[0]), "+f"(c[1]), "+f"(c[2]), "+f"(c[3])
                 : "r"(a0), "r"(a1), "r"(a2), "r"(a3), "r"(b0), "r"(b1));
}

__device__ __forceinline__ void cpa16(void* dst, const void* src) {
    uint32_t d = (uint32_t)__cvta_generic_to_shared(dst);
    asm volatile("cp.async.cg.shared.global [%0], [%1], 16;" :: "r"(d), "l"(src));
}
#define CPA_COMMIT() asm volatile("cp.async.commit_group;")
#define CPA_WAIT(n)  asm volatile("cp.async.wait_group %0;" :: "n"(n))

__device__ __forceinline__ void bar_arrive(unsigned* p) {
    asm volatile("red.release.gpu.global.add.u32 [%0], 1;" :: "l"(p) : "memory");
}
__device__ __forceinline__ unsigned ld_acq(const unsigned* p) {
    unsigned v;
    asm volatile("ld.acquire.gpu.global.u32 %0, [%1];" : "=r"(v) : "l"(p) : "memory");
    return v;
}

// ============================================================
// Kernel 1: a = softmax_d(x^T @ Wx); att = a (all t); WI = a*x
// (recurrent logit term is constant over softmax axis -> cancels)
// ============================================================
__global__ void attn_kernel(const float* __restrict__ x,
                            const float* __restrict__ Wa,
                            float* __restrict__ att)
{
    __shared__ float wx[LL];
    __shared__ float red[DD];
    const int b = blockIdx.x;
    const int d = threadIdx.x;

    if (d < LL) wx[d] = Wa[2 * HH + d];
    __syncthreads();

    const float* xb = x + (size_t)b * LL * DD;
    float ex = 0.f;
#pragma unroll
    for (int l = 0; l < LL; ++l)
        ex += xb[l * DD + d] * wx[l];

    red[d] = ex; __syncthreads();
    for (int s = DD / 2; s > 0; s >>= 1) {
        if (d < s) red[d] = fmaxf(red[d], red[d + s]);
        __syncthreads();
    }
    const float mx = red[0];
    __syncthreads();

    const float e = expf(ex - mx);
    red[d] = e; __syncthreads();
    for (int s = DD / 2; s > 0; s >>= 1) {
        if (d < s) red[d] += red[d + s];
        __syncthreads();
    }
    const float a = e / red[0];

    float* attb = att + (size_t)b * LL * DD;
    float* wib  = g_WI + (size_t)b * LL * DD;
#pragma unroll 4
    for (int t = 0; t < LL; ++t) {
        attb[t * DD + d] = a;
        wib[t * DD + d]  = a * xb[t * DD + d];
    }
}

// ============================================================
// Kernel 2: Gx = WI @ Wih^T + b_ih + b_hh   (16384 x 2048 x 256, tf32)
// ============================================================
__global__ __launch_bounds__(256) void gemm_xproj(
    const float* __restrict__ A,
    const float* __restrict__ Bw,
    const float* __restrict__ b1,
    const float* __restrict__ b2,
    float* __restrict__ C)
{
    __shared__ float As[128 * 36];
    __shared__ float Bs[64 * 36];

    const int tid  = threadIdx.x;
    const int lane = tid & 31, warp = tid >> 5;
    const int qid  = lane >> 2, tig = lane & 3;
    const int wm   = warp >> 1;
    const int wn   = warp & 1;
    const int m0   = blockIdx.y * 128;
    const int n0   = blockIdx.x * 64;

    const int lr = tid >> 3;
    const int lk = (tid & 7) * 4;

    const float* aptr = A  + (size_t)(m0 + lr) * DD + lk;
    const float* bptr = Bw + (size_t)(n0 + lr) * DD + lk;

    float4 pa[4], pb[2];
#pragma unroll
    for (int i = 0; i < 4; ++i) pa[i] = *(const float4*)(aptr + (size_t)i * 32 * DD);
#pragma unroll
    for (int i = 0; i < 2; ++i) pb[i] = *(const float4*)(bptr + (size_t)i * 32 * DD);

    float acc[2][4][4] = {};

    for (int k0 = 0; k0 < DD; k0 += 32) {
#pragma unroll
        for (int i = 0; i < 4; ++i) {
            float* d = &As[(lr + i * 32) * 36 + lk];
            d[0] = __uint_as_float(f2tf32(pa[i].x));
            d[1] = __uint_as_float(f2tf32(pa[i].y));
            d[2] = __uint_as_float(f2tf32(pa[i].z));
            d[3] = __uint_as_float(f2tf32(pa[i].w));
        }
#pragma unroll
        for (int i = 0; i < 2; ++i) {
            float* d = &Bs[(lr + i * 32) * 36 + lk];
            d[0] = __uint_as_float(f2tf32(pb[i].x));
            d[1] = __uint_as_float(f2tf32(pb[i].y));
            d[2] = __uint_as_float(f2tf32(pb[i].z));
            d[3] = __uint_as_float(f2tf32(pb[i].w));
        }
        __syncthreads();

        if (k0 + 32 < DD) {
#pragma unroll
            for (int i = 0; i < 4; ++i) pa[i] = *(const float4*)(aptr + k0 + 32 + (size_t)i * 32 * DD);
#pragma unroll
            for (int i = 0; i < 2; ++i) pb[i] = *(const float4*)(bptr + k0 + 32 + (size_t)i * 32 * DD);
        }

#pragma unroll
        for (int kk = 0; kk < 4; ++kk) {
            uint32_t af[2][4], bf[4][2];
#pragma unroll
            for (int mt = 0; mt < 2; ++mt) {
                const float* s = &As[(wm * 32 + mt * 16 + qid) * 36 + kk * 8 + tig];
                af[mt][0] = __float_as_uint(s[0]);
                af[mt][1] = __float_as_uint(s[8 * 36]);
                af[mt][2] = __float_as_uint(s[4]);
                af[mt][3] = __float_as_uint(s[8 * 36 + 4]);
            }
#pragma unroll
            for (int nt = 0; nt < 4; ++nt) {
                const float* s = &Bs[(wn * 32 + nt * 8 + qid) * 36 + kk * 8 + tig];
                bf[nt][0] = __float_as_uint(s[0]);
                bf[nt][1] = __float_as_uint(s[4]);
            }
#pragma unroll
            for (int mt = 0; mt < 2; ++mt)
#pragma unroll
                for (int nt = 0; nt < 4; ++nt)
                    mma8(acc[mt][nt], af[mt][0], af[mt][1], af[mt][2], af[mt][3],
                         bf[nt][0], bf[nt][1]);
        }
        __syncthreads();
    }

#pragma unroll
    for (int mt = 0; mt < 2; ++mt) {
        const int m = m0 + wm * 32 + mt * 16 + qid;
#pragma unroll
        for (int nt = 0; nt < 4; ++nt) {
            const int n = n0 + wn * 32 + nt * 8 + 2 * tig;
            const float bb0 = b1[n] + b2[n];
            const float bb1 = b1[n + 1] + b2[n + 1];
            float2 o0 = {acc[mt][nt][0] + bb0, acc[mt][nt][1] + bb1};
            float2 o1 = {acc[mt][nt][2] + bb0, acc[mt][nt][3] + bb1};
            *(float2*)(C + (size_t)m * G4 + n)       = o0;
            *(float2*)(C + (size_t)(m + 8) * G4 + n) = o1;
        }
    }
}

// ============================================================
// Kernel 3: PERSISTENT fp16 recurrence.
// 128 blocks = 8 batch groups x 16 unit slices. Block tile:
// 32 batch x 128 gate-cols (32 units x 4 gates), K=512.
// Whh slice resident in smem as fp16 (130 KB). 8 warps:
// gate = warp&3 (32-col group), set = warp>>2 (K parity split).
// Per-group barriers (16 arrivals). c in regs; h fp16 ping-pong.
// ============================================================
#define WHH_H  (128 * 520)                // Whh slice, fp16 halves
#define HCH_H  (32 * 72)                  // one 64-K h chunk, fp16 halves
#define GX_F   (32 * 132)                 // Gx tile, f32
#define GT_F   (2 * 32 * 132)             // 2-plane partial-sum exchange, f32
#define SMEM_REC (WHH_H * 2 + 4 * HCH_H * 2 + GX_F * 4 + GT_F * 4)  // 202240 B

__global__ void __launch_bounds__(256, 1) rec_persistent(
    const float* __restrict__ h0,
    const float* __restrict__ c0,
    const float* __restrict__ Whh,
    const float* __restrict__ Gx,
    float* __restrict__ enc,
    __half* __restrict__ hbuf)
{
    extern __shared__ __align__(16) __half smh[];
    __half* WhhS = smh;                         // [128][520]
    __half* hS   = smh + WHH_H;                 // [4][32][72]
    float*  GxS  = (float*)(smh + WHH_H + 4 * HCH_H);  // [32][132]
    float*  Gt   = GxS + GX_F;                  // [2][32][132]

    const int tid  = threadIdx.x;
    const int lane = tid & 31, warp = tid >> 5;
    const int qid  = lane >> 2, tig = lane & 3;
    const int set  = warp >> 2;                 // K parity
    const int gate = warp & 3;                  // 32-col group
    const int bid  = blockIdx.x;
    const int grp  = bid >> 4;                  // batch group 0..7
    const int m0   = grp * MB;
    const int u0   = (bid & 15) * UB;

    // ---- Whh slice -> smem fp16 (once). row r = gate'*32+uu ----
    for (int idx = tid; idx < 128 * 128; idx += 256) {
        const int r = idx >> 7, kq = (idx & 127) * 4;
        const float4 v = *(const float4*)&Whh[(size_t)((r >> 5) * HH + u0 + (r & 31)) * HH + kq];
        *(__half2*)&WhhS[r * 520 + kq]     = __floats2half2_rn(v.x, v.y);
        *(__half2*)&WhhS[r * 520 + kq + 2] = __floats2half2_rn(v.z, v.w);
    }

    // ---- h(0) slice -> fp16 ping buffer 0 ----
    for (int idx = tid; idx < MB * UB; idx += 256) {
        const int b = idx >> 5, uu = idx & 31;
        hbuf[(size_t)(m0 + b) * HH + u0 + uu] =
            __float2half_rn(h0[(size_t)(m0 + b) * HH + u0 + uu]);
    }

    // ---- c slice in registers ----
    const int cb = tid >> 3;                    // 0..31 (batch rel)
    const int cu = (tid & 7) * 4;               // unit rel, step 4
    float creg[4];
    {
        const float4 cv = *(const float4*)&c0[(size_t)(m0 + cb) * HH + u0 + cu];
        creg[0] = cv.x; creg[1] = cv.y; creg[2] = cv.z; creg[3] = cv.w;
    }

    for (int t = 0; t < LL; ++t) {
        const __half* hsrc = hbuf + (size_t)(t & 1) * BB * HH;
        __half*       hdst = hbuf + (size_t)((t + 1) & 1) * BB * HH;

        // Gx prefetch for this step (static input; pre-barrier)
        {
            const float* gbase = Gx + ((size_t)m0 * LL + t) * G4 + u0;
#pragma unroll
            for (int i = 0; i < 4; ++i) {
                const int idx = tid + i * 256;
                const int b = idx >> 5, g = (idx >> 3) & 3, q = (idx & 7) * 4;
                cpa16(&GxS[b * 132 + g * 32 + q],
                      gbase + (size_t)b * LL * G4 + g * HH + q);
            }
            CPA_COMMIT();
        }

        // ---- per-group barrier: h(t) from the 16 peer blocks ----
        if (tid == 0) {
            unsigned* ctr = &g_ctr[grp][t];
            bar_arrive(ctr);
            while (ld_acq(ctr) < 16u) __nanosleep(32);
        }
        __syncthreads();

        // ---- issue h chunks 0..2 (fp16, 4 KB each: 1 cpa16/thread) ----
#pragma unroll
        for (int p = 0; p < 3; ++p) {
            const int r = tid >> 3, q8 = (tid & 7) * 8;
            cpa16(&hS[p * HCH_H + r * 72 + q8],
                  hsrc + (size_t)(m0 + r) * HH + p * 64 + q8);
            CPA_COMMIT();
        }

        float acc[2][4][4] = {};

#pragma unroll
        for (int kc = 0; kc < 8; ++kc) {
            if (kc < 6)      { CPA_WAIT(2); }
            else if (kc == 6){ CPA_WAIT(1); }
            else             { CPA_WAIT(0); }
            __syncthreads();

            if (kc < 5) {                       // issue chunk kc+3
                const int r = tid >> 3, q8 = (tid & 7) * 8;
                cpa16(&hS[((kc + 3) & 3) * HCH_H + r * 72 + q8],
                      hsrc + (size_t)(m0 + r) * HH + (kc + 3) * 64 + q8);
                CPA_COMMIT();
            }

            if (set == (kc & 1)) {              // K-split: this warp-set's chunk
                const __half* hA = hS + (kc & 3) * HCH_H;
                const __half* wB = WhhS + kc * 64;
#pragma unroll
                for (int kk = 0; kk < 4; ++kk) {
                    uint32_t af[2][4], bf[4][2];
#pragma unroll
                    for (int mt = 0; mt < 2; ++mt) {
                        const __half* s = hA + (mt * 16 + qid) * 72 + kk * 16 + tig * 2;
                        af[mt][0] = *(const uint32_t*)(s);
                        af[mt][1] = *(const uint32_t*)(s + 8 * 72);
                        af[mt][2] = *(const uint32_t*)(s + 8);
                        af[mt][3] = *(const uint32_t*)(s + 8 * 72 + 8);
                    }
#pragma unroll
                    for (int nt = 0; nt < 4; ++nt) {
                        const __half* s = wB + (gate * 32 + nt * 8 + qid) * 520 + kk * 16 + tig * 2;
                        bf[nt][0] = *(const uint32_t*)(s);
                        bf[nt][1] = *(const uint32_t*)(s + 8);
                    }
#pragma unroll
                    for (int mt = 0; mt < 2; ++mt)
#pragma unroll
                        for (int nt = 0; nt < 4; ++nt)
                            mma16(acc[mt][nt], af[mt][0], af[mt][1], af[mt][2], af[mt][3],
                                  bf[nt][0], bf[nt][1]);
                }
            }
        }

        // ---- epilogue: write partials to 2-plane Gt ----
        {
            float* Gp = Gt + set * (32 * 132);
#pragma unroll
            for (int mt = 0; mt < 2; ++mt) {
                const int rl = mt * 16 + qid;
#pragma unroll
                for (int nt = 0; nt < 4; ++nt) {
                    const int cl = gate * 32 + nt * 8 + tig * 2;
                    *(float2*)&Gp[rl * 132 + cl]       = make_float2(acc[mt][nt][0], acc[mt][nt][1]);
                    *(float2*)&Gp[(rl + 8) * 132 + cl] = make_float2(acc[mt][nt][2], acc[mt][nt][3]);
                }
            }
        }
        __syncthreads();

        // ---- LSTM cell: sum partials + Gx; c in regs ----
        {
            float gv[4][4];
#pragma unroll
            for (int g = 0; g < 4; ++g) {
                const int off = cb * 132 + g * 32 + cu;
                const float4 p0 = *(const float4*)&Gt[off];
                const float4 p1 = *(const float4*)&Gt[32 * 132 + off];
                const float4 px = *(const float4*)&GxS[off];
                gv[g][0] = p0.x + p1.x + px.x;
                gv[g][1] = p0.y + p1.y + px.y;
                gv[g][2] = p0.z + p1.z + px.z;
                gv[g][3] = p0.w + p1.w + px.w;
            }

            float4 ho;
            float* hop = &ho.x;
            __half hr[4];
#pragma unroll
            for (int k = 0; k < 4; ++k) {
                const float si = 1.f / (1.f + expf(-gv[0][k]));
                const float sf = 1.f / (1.f + expf(-gv[1][k]));
                const float so = 1.f / (1.f + expf(-gv[3][k]));
                const float cn = sf * creg[k] + si * tanhf(gv[2][k]);
                const float hn = so * tanhf(cn);
                creg[k] = cn;
                hop[k] = hn;
                hr[k] = __float2half_rn(hn);
            }
            *(float4*)(enc + (size_t)(m0 + cb) * LL * HH + (size_t)t * HH + u0 + cu) = ho;
            *(uint2*)(hdst + (size_t)(m0 + cb) * HH + u0 + cu) = *(const uint2*)hr;
        }
        __syncthreads();   // GxS/Gt safe for next iter; hdst done before next arrive
    }
}

// ============================================================
// Launch
// ============================================================
extern "C" void kernel_launch(void* const* d_in, const int* in_sizes, int n_in,
                              void* d_out, int out_size)
{
    (void)in_sizes; (void)n_in; (void)out_size;
    const float* x   = (const float*)d_in[0];
    const float* h0  = (const float*)d_in[1];
    const float* c0  = (const float*)d_in[2];
    const float* Wih = (const float*)d_in[3];
    const float* Whh = (const float*)d_in[4];
    const float* bih = (const float*)d_in[5];
    const float* bhh = (const float*)d_in[6];
    const float* Wa  = (const float*)d_in[7];
    // d_in[8] = ba: cancels inside softmax, never read.

    float* att = (float*)d_out;                       // (B, L, D)
    float* enc = att + (size_t)BB * LL * DD;          // (B, L, H)

    float *wi, *gx;
    __half* hbuf;
    void* ctr;
    cudaGetSymbolAddress((void**)&wi,   g_WI);
    cudaGetSymbolAddress((void**)&gx,   g_Gx);
    cudaGetSymbolAddress((void**)&hbuf, g_h);
    cudaGetSymbolAddress(&ctr,          g_ctr);

    static int smem_set = 0;
    if (!smem_set) {
        cudaFuncSetAttribute(rec_persistent,
                             cudaFuncAttributeMaxDynamicSharedMemorySize, SMEM_REC);
        smem_set = 1;
    }

    // 0) zero per-step barrier counters (captured memset node)
    cudaMemsetAsync(ctr, 0, sizeof(unsigned) * NGRP * LL);

    // 1) attention weights + att output + WI scratch
    attn_kernel<<<BB, DD>>>(x, Wa, att);

    // 2) big parallel input projection (tf32 tensor cores)
    {
        dim3 grid(G4 / 64, (BB * LL) / 128);
        gemm_xproj<<<grid, 256>>>(wi, Wih, bih, bhh, gx);
    }

    // 3) whole recurrence in ONE persistent fp16 kernel
    rec_persistent<<<NBLK, 256, SMEM_REC>>>(h0, c0, Whh, gx, enc, hbuf);
}

// round 7
// speedup vs baseline: 5.2331x; 1.1024x over previous
#include <cuda_runtime.h>
#include <cuda_fp16.h>
#include <math.h>
#include <stdint.h>

// Problem dims (fixed)
#define BB   256      // batch
#define LL   64       // seq len
#define DD   256      // input dim
#define HH   512      // hidden
#define G4   2048     // 4*H

#define NBLK 128      // persistent grid: 8 batch groups x 16 unit slices
#define NGRP 8        // barrier domains (16 blocks each)
#define MB   32       // batch rows per block
#define UB   32       // units per block (x4 gates = 128 gate-cols)

// -------- scratch (device globals: allocation-free) --------
__device__ float  g_a[BB * DD];                   // attention weights a[b,d]
__device__ float  g_Gx[(size_t)BB * LL * G4];     // 128 MB
__device__ __half g_h[2 * BB * HH];               // ping-pong h (fp16)
__device__ unsigned g_ctr[NGRP][LL];              // per-group per-step arrival counters

// ---------- helpers ----------
__device__ __forceinline__ uint32_t f2tf32(float f) {
    uint32_t u;
    asm("cvt.rna.tf32.f32 %0, %1;" : "=r"(u) : "f"(f));
    return u;
}

__device__ __forceinline__ void mma8(float* c,
                                     uint32_t a0, uint32_t a1, uint32_t a2, uint32_t a3,
                                     uint32_t b0, uint32_t b1)
{
    asm volatile("mma.sync.aligned.m16n8k8.row.col.f32.tf32.tf32.f32 "
                 "{%0,%1,%2,%3},{%4,%5,%6,%7},{%8,%9},{%0,%1,%2,%3};"
                 : "+f"(c[0]), "+f"(c[1]), "+f"(c[2]), "+f"(c[3])
                 : "r"(a0), "r"(a1), "r"(a2), "r"(a3), "r"(b0), "r"(b1));
}

__device__ __forceinline__ void mma16(float* c,
                                      uint32_t a0, uint32_t a1, uint32_t a2, uint32_t a3,
                                      uint32_t b0, uint32_t b1)
{
    asm volatile("mma.sync.aligned.m16n8k16.row.col.f32.f16.f16.f32 "
                 "{%0,%1,%2,%3},{%4,%5,%6,%7},{%8,%9},{%0,%1,%2,%3};"
                 : "+f"(c[0]), "+f"(c[1]), "+f"(c[2]), "+f"(c[3])
                 : "r"(a0), "r"(a1), "r"(a2), "r"(a3), "r"(b0), "r"(b1));
}

__device__ __forceinline__ void cpa16(void* dst, const void* src) {
    uint32_t d = (uint32_t)__cvta_generic_to_shared(dst);
    asm volatile("cp.async.cg.shared.global [%0], [%1], 16;" :: "r"(d), "l"(src));
}
#define CPA_COMMIT() asm volatile("cp.async.commit_group;")
#define CPA_WAIT(n)  asm volatile("cp.async.wait_group %0;" :: "n"(n))

__device__ __forceinline__ void bar_arrive(unsigned* p) {
    asm volatile("red.release.gpu.global.add.u32 [%0], 1;" :: "l"(p) : "memory");
}
__device__ __forceinline__ unsigned ld_acq(const unsigned* p) {
    unsigned v;
    asm volatile("ld.acquire.gpu.global.u32 %0, [%1];" : "=r"(v) : "l"(p) : "memory");
    return v;
}

// fast sigmoid / tanh (MUFU ex2 + rcp; rel err ~1e-6)
__device__ __forceinline__ float sigf(float x) {
    return __fdividef(1.f, 1.f + __expf(-x));
}
__device__ __forceinline__ float tanhfast(float x) {
    return __fmaf_rn(2.f, __fdividef(1.f, 1.f + __expf(-2.f * x)), -1.f);
}

// ============================================================
// Kernel 1: a = softmax_d(x^T @ Wx); att = a (all t); store a[b,d]
// (recurrent logit term is constant over softmax axis -> cancels)
// ============================================================
__global__ void attn_kernel(const float* __restrict__ x,
                            const float* __restrict__ Wa,
                            float* __restrict__ att)
{
    __shared__ float wx[LL];
    __shared__ float red[DD];
    const int b = blockIdx.x;
    const int d = threadIdx.x;

    if (d < LL) wx[d] = Wa[2 * HH + d];
    __syncthreads();

    const float* xb = x + (size_t)b * LL * DD;
    float ex = 0.f;
#pragma unroll
    for (int l = 0; l < LL; ++l)
        ex += xb[l * DD + d] * wx[l];

    red[d] = ex; __syncthreads();
    for (int s = DD / 2; s > 0; s >>= 1) {
        if (d < s) red[d] = fmaxf(red[d], red[d + s]);
        __syncthreads();
    }
    const float mx = red[0];
    __syncthreads();

    const float e = expf(ex - mx);
    red[d] = e; __syncthreads();
    for (int s = DD / 2; s > 0; s >>= 1) {
        if (d < s) red[d] += red[d + s];
        __syncthreads();
    }
    const float a = e / red[0];

    g_a[b * DD + d] = a;

    float* attb = att + (size_t)b * LL * DD;
#pragma unroll 8
    for (int t = 0; t < LL; ++t)
        attb[t * DD + d] = a;
}

// ============================================================
// Kernel 2: Gx = (a .* x) @ Wih^T + b_ih + b_hh  (16384x2048x256, tf32)
// a-scaling folded into the A-tile smem fill (g_WI eliminated).
// ============================================================
__global__ __launch_bounds__(256) void gemm_xproj(
    const float* __restrict__ X,
    const float* __restrict__ Bw,
    const float* __restrict__ b1,
    const float* __restrict__ b2,
    float* __restrict__ C)
{
    __shared__ float As[128 * 36];
    __shared__ float Bs[64 * 36];

    const int tid  = threadIdx.x;
    const int lane = tid & 31, warp = tid >> 5;
    const int qid  = lane >> 2, tig = lane & 3;
    const int wm   = warp >> 1;
    const int wn   = warp & 1;
    const int m0   = blockIdx.y * 128;
    const int n0   = blockIdx.x * 64;

    const int lr = tid >> 3;
    const int lk = (tid & 7) * 4;

    const float* aptr = X  + (size_t)(m0 + lr) * DD + lk;
    const float* bptr = Bw + (size_t)(n0 + lr) * DD + lk;
    int brow[4];
#pragma unroll
    for (int i = 0; i < 4; ++i) brow[i] = (m0 + lr + i * 32) >> 6;   // batch of row

    float4 pa[4], sa[4], pb[2];
#pragma unroll
    for (int i = 0; i < 4; ++i) {
        pa[i] = *(const float4*)(aptr + (size_t)i * 32 * DD);
        sa[i] = *(const float4*)(g_a + brow[i] * DD + lk);
    }
#pragma unroll
    for (int i = 0; i < 2; ++i) pb[i] = *(const float4*)(bptr + (size_t)i * 32 * DD);

    float acc[2][4][4] = {};

    for (int k0 = 0; k0 < DD; k0 += 32) {
#pragma unroll
        for (int i = 0; i < 4; ++i) {
            float* d = &As[(lr + i * 32) * 36 + lk];
            d[0] = __uint_as_float(f2tf32(pa[i].x * sa[i].x));
            d[1] = __uint_as_float(f2tf32(pa[i].y * sa[i].y));
            d[2] = __uint_as_float(f2tf32(pa[i].z * sa[i].z));
            d[3] = __uint_as_float(f2tf32(pa[i].w * sa[i].w));
        }
#pragma unroll
        for (int i = 0; i < 2; ++i) {
            float* d = &Bs[(lr + i * 32) * 36 + lk];
            d[0] = __uint_as_float(f2tf32(pb[i].x));
            d[1] = __uint_as_float(f2tf32(pb[i].y));
            d[2] = __uint_as_float(f2tf32(pb[i].z));
            d[3] = __uint_as_float(f2tf32(pb[i].w));
        }
        __syncthreads();

        if (k0 + 32 < DD) {
#pragma unroll
            for (int i = 0; i < 4; ++i) {
                pa[i] = *(const float4*)(aptr + k0 + 32 + (size_t)i * 32 * DD);
                sa[i] = *(const float4*)(g_a + brow[i] * DD + k0 + 32 + lk);
            }
#pragma unroll
            for (int i = 0; i < 2; ++i) pb[i] = *(const float4*)(bptr + k0 + 32 + (size_t)i * 32 * DD);
        }

#pragma unroll
        for (int kk = 0; kk < 4; ++kk) {
            uint32_t af[2][4], bf[4][2];
#pragma unroll
            for (int mt = 0; mt < 2; ++mt) {
                const float* s = &As[(wm * 32 + mt * 16 + qid) * 36 + kk * 8 + tig];
                af[mt][0] = __float_as_uint(s[0]);
                af[mt][1] = __float_as_uint(s[8 * 36]);
                af[mt][2] = __float_as_uint(s[4]);
                af[mt][3] = __float_as_uint(s[8 * 36 + 4]);
            }
#pragma unroll
            for (int nt = 0; nt < 4; ++nt) {
                const float* s = &Bs[(wn * 32 + nt * 8 + qid) * 36 + kk * 8 + tig];
                bf[nt][0] = __float_as_uint(s[0]);
                bf[nt][1] = __float_as_uint(s[4]);
            }
#pragma unroll
            for (int mt = 0; mt < 2; ++mt)
#pragma unroll
                for (int nt = 0; nt < 4; ++nt)
                    mma8(acc[mt][nt], af[mt][0], af[mt][1], af[mt][2], af[mt][3],
                         bf[nt][0], bf[nt][1]);
        }
        __syncthreads();
    }

#pragma unroll
    for (int mt = 0; mt < 2; ++mt) {
        const int m = m0 + wm * 32 + mt * 16 + qid;
#pragma unroll
        for (int nt = 0; nt < 4; ++nt) {
            const int n = n0 + wn * 32 + nt * 8 + 2 * tig;
            const float bb0 = b1[n] + b2[n];
            const float bb1 = b1[n + 1] + b2[n + 1];
            float2 o0 = {acc[mt][nt][0] + bb0, acc[mt][nt][1] + bb1};
            float2 o1 = {acc[mt][nt][2] + bb0, acc[mt][nt][3] + bb1};
            *(float2*)(C + (size_t)m * G4 + n)       = o0;
            *(float2*)(C + (size_t)(m + 8) * G4 + n) = o1;
        }
    }
}

// ============================================================
// Kernel 3: PERSISTENT fp16 recurrence, sync-minimal.
// 128 blocks = 8 batch groups x 16 unit slices; block tile
// 32 batch x 128 gate-cols, K=512. Whh resident in smem (fp16).
// Per step: preload ALL h chunks (one wait, one sync), sync-free
// MMA loop (K-parity warp sets), 3 syncthreads total per step.
// ============================================================
#define WHH_H  (128 * 520)                // Whh slice, fp16 halves
#define HCH_H  (32 * 72)                  // one 64-K h chunk, fp16 halves
#define GX_F   (32 * 132)                 // Gx tile, f32
#define GT_F   (2 * 32 * 132)             // 2-plane partial-sum exchange, f32
#define SMEM_REC (WHH_H * 2 + 8 * HCH_H * 2 + GX_F * 4 + GT_F * 4)  // 220672 B

__global__ void __launch_bounds__(256, 1) rec_persistent(
    const float* __restrict__ h0,
    const float* __restrict__ c0,
    const float* __restrict__ Whh,
    const float* __restrict__ Gx,
    float* __restrict__ enc,
    __half* __restrict__ hbuf)
{
    extern __shared__ __align__(16) __half smh[];
    __half* WhhS = smh;                         // [128][520]
    __half* hS   = smh + WHH_H;                 // [8][32][72]
    float*  GxS  = (float*)(smh + WHH_H + 8 * HCH_H);  // [32][132]
    float*  Gt   = GxS + GX_F;                  // [2][32][132]

    const int tid  = threadIdx.x;
    const int lane = tid & 31, warp = tid >> 5;
    const int qid  = lane >> 2, tig = lane & 3;
    const int set  = warp >> 2;                 // K parity
    const int gate = warp & 3;                  // 32-col group
    const int bid  = blockIdx.x;
    const int grp  = bid >> 4;                  // batch group 0..7
    const int m0   = grp * MB;
    const int u0   = (bid & 15) * UB;

    // ---- Whh slice -> smem fp16 (once) ----
    for (int idx = tid; idx < 128 * 128; idx += 256) {
        const int r = idx >> 7, kq = (idx & 127) * 4;
        const float4 v = *(const float4*)&Whh[(size_t)((r >> 5) * HH + u0 + (r & 31)) * HH + kq];
        *(__half2*)&WhhS[r * 520 + kq]     = __floats2half2_rn(v.x, v.y);
        *(__half2*)&WhhS[r * 520 + kq + 2] = __floats2half2_rn(v.z, v.w);
    }

    // ---- h(0) slice -> fp16 ping buffer 0 ----
    for (int idx = tid; idx < MB * UB; idx += 256) {
        const int b = idx >> 5, uu = idx & 31;
        hbuf[(size_t)(m0 + b) * HH + u0 + uu] =
            __float2half_rn(h0[(size_t)(m0 + b) * HH + u0 + uu]);
    }

    // ---- c slice in registers ----
    const int cb = tid >> 3;                    // 0..31 (batch rel)
    const int cu = (tid & 7) * 4;               // unit rel, step 4
    float creg[4];
    {
        const float4 cv = *(const float4*)&c0[(size_t)(m0 + cb) * HH + u0 + cu];
        creg[0] = cv.x; creg[1] = cv.y; creg[2] = cv.z; creg[3] = cv.w;
    }

    __syncthreads();                            // h(0)+Whh writes done block-wide
    if (tid == 0) bar_arrive(&g_ctr[grp][0]);   // publish h(0)

    const int hr8 = tid >> 3, hq8 = (tid & 7) * 8;   // h-chunk load indices

    for (int t = 0; t < LL; ++t) {
        const __half* hsrc = hbuf + (size_t)(t & 1) * BB * HH;
        __half*       hdst = hbuf + (size_t)((t + 1) & 1) * BB * HH;

        // Gx prefetch for this step (static input; overlaps barrier wait)
        {
            const float* gbase = Gx + ((size_t)m0 * LL + t) * G4 + u0;
#pragma unroll
            for (int i = 0; i < 4; ++i) {
                const int idx = tid + i * 256;
                const int b = idx >> 5, g = (idx >> 3) & 3, q = (idx & 7) * 4;
                cpa16(&GxS[b * 132 + g * 32 + q],
                      gbase + (size_t)b * LL * G4 + g * HH + q);
            }
            CPA_COMMIT();
        }

        // ---- per-group barrier: h(t) from the 16 peer blocks ----
        if (tid == 0) {
            const unsigned* ctr = &g_ctr[grp][t];
            while (ld_acq(ctr) < 16u) {}
        }
        __syncthreads();

        // ---- preload ALL 8 h chunks; one wait, one sync ----
#pragma unroll
        for (int p = 0; p < 8; ++p)
            cpa16(&hS[p * HCH_H + hr8 * 72 + hq8],
                  hsrc + (size_t)(m0 + hr8) * HH + p * 64 + hq8);
        CPA_COMMIT();
        CPA_WAIT(0);
        __syncthreads();                        // everything resident

        // ---- sync-free MMA loop: set 0 -> even chunks, set 1 -> odd ----
        float acc[2][4][4] = {};
#pragma unroll
        for (int j = 0; j < 4; ++j) {
            const int kc = j * 2 + set;
            const __half* hA = hS + kc * HCH_H;
            const __half* wB = WhhS + kc * 64;
#pragma unroll
            for (int kk = 0; kk < 4; ++kk) {
                uint32_t af[2][4], bf[4][2];
#pragma unroll
                for (int mt = 0; mt < 2; ++mt) {
                    const __half* s = hA + (mt * 16 + qid) * 72 + kk * 16 + tig * 2;
                    af[mt][0] = *(const uint32_t*)(s);
                    af[mt][1] = *(const uint32_t*)(s + 8 * 72);
                    af[mt][2] = *(const uint32_t*)(s + 8);
                    af[mt][3] = *(const uint32_t*)(s + 8 * 72 + 8);
                }
#pragma unroll
                for (int nt = 0; nt < 4; ++nt) {
                    const __half* s = wB + (gate * 32 + nt * 8 + qid) * 520 + kk * 16 + tig * 2;
                    bf[nt][0] = *(const uint32_t*)(s);
                    bf[nt][1] = *(const uint32_t*)(s + 8);
                }
#pragma unroll
                for (int mt = 0; mt < 2; ++mt)
#pragma unroll
                    for (int nt = 0; nt < 4; ++nt)
                        mma16(acc[mt][nt], af[mt][0], af[mt][1], af[mt][2], af[mt][3],
                              bf[nt][0], bf[nt][1]);
            }
        }

        // ---- epilogue: partials -> 2-plane Gt (disjoint regions, no pre-sync) ----
        {
            float* Gp = Gt + set * (32 * 132);
#pragma unroll
            for (int mt = 0; mt < 2; ++mt) {
                const int rl = mt * 16 + qid;
#pragma unroll
                for (int nt = 0; nt < 4; ++nt) {
                    const int cl = gate * 32 + nt * 8 + tig * 2;
                    *(float2*)&Gp[rl * 132 + cl]       = make_float2(acc[mt][nt][0], acc[mt][nt][1]);
                    *(float2*)&Gp[(rl + 8) * 132 + cl] = make_float2(acc[mt][nt][2], acc[mt][nt][3]);
                }
            }
        }
        __syncthreads();

        // ---- LSTM cell: sum partials + Gx; fast transcendentals ----
        {
            float gv[4][4];
#pragma unroll
            for (int g = 0; g < 4; ++g) {
                const int off = cb * 132 + g * 32 + cu;
                const float4 p0 = *(const float4*)&Gt[off];
                const float4 p1 = *(const float4*)&Gt[32 * 132 + off];
                const float4 px = *(const float4*)&GxS[off];
                gv[g][0] = p0.x + p1.x + px.x;
                gv[g][1] = p0.y + p1.y + px.y;
                gv[g][2] = p0.z + p1.z + px.z;
                gv[g][3] = p0.w + p1.w + px.w;
            }

            float4 ho;
            float* hop = &ho.x;
            __half hr[4];
#pragma unroll
            for (int k = 0; k < 4; ++k) {
                const float si = sigf(gv[0][k]);
                const float sf = sigf(gv[1][k]);
                const float so = sigf(gv[3][k]);
                const float cn = sf * creg[k] + si * tanhfast(gv[2][k]);
                const float hn = so * tanhfast(cn);
                creg[k] = cn;
                hop[k] = hn;
                hr[k] = __float2half_rn(hn);
            }
            *(float4*)(enc + (size_t)(m0 + cb) * LL * HH + (size_t)t * HH + u0 + cu) = ho;
            *(uint2*)(hdst + (size_t)(m0 + cb) * HH + u0 + cu) = *(const uint2*)hr;
        }
        __syncthreads();                        // hdst + GxS/Gt consumption done
        if (tid == 0 && t + 1 < LL) bar_arrive(&g_ctr[grp][t + 1]);
    }
}

// ============================================================
// Launch
// ============================================================
extern "C" void kernel_launch(void* const* d_in, const int* in_sizes, int n_in,
                              void* d_out, int out_size)
{
    (void)in_sizes; (void)n_in; (void)out_size;
    const float* x   = (const float*)d_in[0];
    const float* h0  = (const float*)d_in[1];
    const float* c0  = (const float*)d_in[2];
    const float* Wih = (const float*)d_in[3];
    const float* Whh = (const float*)d_in[4];
    const float* bih = (const float*)d_in[5];
    const float* bhh = (const float*)d_in[6];
    const float* Wa  = (const float*)d_in[7];
    // d_in[8] = ba: cancels inside softmax, never read.

    float* att = (float*)d_out;                       // (B, L, D)
    float* enc = att + (size_t)BB * LL * DD;          // (B, L, H)

    float *gx;
    __half* hbuf;
    void* ctr;
    cudaGetSymbolAddress((void**)&gx,   g_Gx);
    cudaGetSymbolAddress((void**)&hbuf, g_h);
    cudaGetSymbolAddress(&ctr,          g_ctr);

    static int smem_set = 0;
    if (!smem_set) {
        cudaFuncSetAttribute(rec_persistent,
                             cudaFuncAttributeMaxDynamicSharedMemorySize, SMEM_REC);
        smem_set = 1;
    }

    // 0) zero per-step barrier counters (captured memset node)
    cudaMemsetAsync(ctr, 0, sizeof(unsigned) * NGRP * LL);

    // 1) attention weights a + att output
    attn_kernel<<<BB, DD>>>(x, Wa, att);

    // 2) input projection with fused a-scaling (tf32 tensor cores)
    {
        dim3 grid(G4 / 64, (BB * LL) / 128);
        gemm_xproj<<<grid, 256>>>(x, Wih, bih, bhh, gx);
    }

    // 3) whole recurrence in ONE persistent fp16 kernel
    rec_persistent<<<NBLK, 256, SMEM_REC>>>(h0, c0, Whh, gx, enc, hbuf);
}

// round 11
// speedup vs baseline: 5.4424x; 1.0400x over previous
#include <cuda_runtime.h>
#include <cuda_fp16.h>
#include <math.h>
#include <stdint.h>

// Problem dims (fixed)
#define BB   256      // batch
#define LL   64       // seq len
#define DD   256      // input dim
#define HH   512      // hidden
#define G4   2048     // 4*H

#define NBLK 128      // persistent grid: 8 batch groups x 16 unit slices
#define NGRP 8        // barrier domains (16 blocks each)
#define MB   32       // batch rows per block
#define UB   32       // units per block (x4 gates = 128 gate-cols)

// -------- scratch (device globals: allocation-free) --------
__device__ float  g_a[BB * DD];                   // attention weights a[b,d]
__device__ float  g_Gx[(size_t)BB * LL * G4];     // 128 MB
__device__ __half g_h[2 * BB * HH];               // ping-pong h (fp16)
__device__ unsigned g_ctr[NGRP][LL];              // per-group per-step arrival counters

// ---------- helpers ----------
__device__ __forceinline__ uint32_t f2tf32(float f) {
    uint32_t u;
    asm("cvt.rna.tf32.f32 %0, %1;" : "=r"(u) : "f"(f));
    return u;
}

__device__ __forceinline__ void mma8(float* c,
                                     uint32_t a0, uint32_t a1, uint32_t a2, uint32_t a3,
                                     uint32_t b0, uint32_t b1)
{
    asm volatile("mma.sync.aligned.m16n8k8.row.col.f32.tf32.tf32.f32 "
                 "{%0,%1,%2,%3},{%4,%5,%6,%7},{%8,%9},{%0,%1,%2,%3};"
                 : "+f"(c[0]), "+f"(c[1]), "+f"(c[2]), "+f"(c[3])
                 : "r"(a0), "r"(a1), "r"(a2), "r"(a3), "r"(b0), "r"(b1));
}

__device__ __forceinline__ void mma16(float* c,
                                      uint32_t a0, uint32_t a1, uint32_t a2, uint32_t a3,
                                      uint32_t b0, uint32_t b1)
{
    asm volatile("mma.sync.aligned.m16n8k16.row.col.f32.f16.f16.f32 "
                 "{%0,%1,%2,%3},{%4,%5,%6,%7},{%8,%9},{%0,%1,%2,%3};"
                 : "+f"(c[0]), "+f"(c[1]), "+f"(c[2]), "+f"(c[3])
                 : "r"(a0), "r"(a1), "r"(a2), "r"(a3), "r"(b0), "r"(b1));
}

__device__ __forceinline__ void cpa16(void* dst, const void* src) {
    uint32_t d = (uint32_t)__cvta_generic_to_shared(dst);
    asm volatile("cp.async.cg.shared.global [%0], [%1], 16;" :: "r"(d), "l"(src));
}
#define CPA_COMMIT() asm volatile("cp.async.commit_group;")
#define CPA_WAIT0()  asm volatile("cp.async.wait_group 0;")

__device__ __forceinline__ void bar_arrive(unsigned* p) {
    asm volatile("red.release.gpu.global.add.u32 [%0], 1;" :: "l"(p) : "memory");
}
__device__ __forceinline__ unsigned ld_acq(const unsigned* p) {
    unsigned v;
    asm volatile("ld.acquire.gpu.global.u32 %0, [%1];" : "=r"(v) : "l"(p) : "memory");
    return v;
}

__device__ __forceinline__ float sigf(float x) {
    return __fdividef(1.f, 1.f + __expf(-x));
}
__device__ __forceinline__ float tanhfast(float x) {
    return __fmaf_rn(2.f, __fdividef(1.f, 1.f + __expf(-2.f * x)), -1.f);
}

// ============================================================
// Kernel 1: a = softmax_d(x^T @ Wx); att = a (all t); store a[b,d]
// (recurrent logit term is constant over softmax axis -> cancels)
// ============================================================
__global__ void attn_kernel(const float* __restrict__ x,
                            const float* __restrict__ Wa,
                            float* __restrict__ att)
{
    __shared__ float wx[LL];
    __shared__ float red[DD];
    const int b = blockIdx.x;
    const int d = threadIdx.x;

    if (d < LL) wx[d] = Wa[2 * HH + d];
    __syncthreads();

    const float* xb = x + (size_t)b * LL * DD;
    float ex = 0.f;
#pragma unroll
    for (int l = 0; l < LL; ++l)
        ex += xb[l * DD + d] * wx[l];

    red[d] = ex; __syncthreads();
    for (int s = DD / 2; s > 0; s >>= 1) {
        if (d < s) red[d] = fmaxf(red[d], red[d + s]);
        __syncthreads();
    }
    const float mx = red[0];
    __syncthreads();

    const float e = expf(ex - mx);
    red[d] = e; __syncthreads();
    for (int s = DD / 2; s > 0; s >>= 1) {
        if (d < s) red[d] += red[d + s];
        __syncthreads();
    }
    const float a = e / red[0];

    g_a[b * DD + d] = a;

    __syncthreads();                 // red[0] consumed by all before reuse
    red[d] = a;                      // broadcast a for vectorized stores
    __syncthreads();

    float* attb = att + (size_t)b * LL * DD;
    const int d4 = (d & 63) * 4;
    const float4 av = *(const float4*)&red[d4];
#pragma unroll
    for (int tt = d >> 6; tt < LL; tt += 4)
        *(float4*)&attb[tt * DD + d4] = av;
}

// ============================================================
// Kernel 2: Gx = (a .* x) @ Wih^T + b_ih + b_hh  (16384x2048x256, tf32)
// a-scaling folded into the A-tile smem fill.
// ============================================================
__global__ __launch_bounds__(256) void gemm_xproj(
    const float* __restrict__ X,
    const float* __restrict__ Bw,
    const float* __restrict__ b1,
    const float* __restrict__ b2,
    float* __restrict__ C)
{
    __shared__ float As[128 * 36];
    __shared__ float Bs[64 * 36];

    const int tid  = threadIdx.x;
    const int lane = tid & 31, warp = tid >> 5;
    const int qid  = lane >> 2, tig = lane & 3;
    const int wm   = warp >> 1;
    const int wn   = warp & 1;
    const int m0   = blockIdx.y * 128;
    const int n0   = blockIdx.x * 64;

    const int lr = tid >> 3;
    const int lk = (tid & 7) * 4;

    const float* aptr = X  + (size_t)(m0 + lr) * DD + lk;
    const float* bptr = Bw + (size_t)(n0 + lr) * DD + lk;
    int brow[4];
#pragma unroll
    for (int i = 0; i < 4; ++i) brow[i] = (m0 + lr + i * 32) >> 6;

    float4 pa[4], sa[4], pb[2];
#pragma unroll
    for (int i = 0; i < 4; ++i) {
        pa[i] = *(const float4*)(aptr + (size_t)i * 32 * DD);
        sa[i] = *(const float4*)(g_a + brow[i] * DD + lk);
    }
#pragma unroll
    for (int i = 0; i < 2; ++i) pb[i] = *(const float4*)(bptr + (size_t)i * 32 * DD);

    float acc[2][4][4] = {};

    for (int k0 = 0; k0 < DD; k0 += 32) {
#pragma unroll
        for (int i = 0; i < 4; ++i) {
            float* d = &As[(lr + i * 32) * 36 + lk];
            d[0] = __uint_as_float(f2tf32(pa[i].x * sa[i].x));
            d[1] = __uint_as_float(f2tf32(pa[i].y * sa[i].y));
            d[2] = __uint_as_float(f2tf32(pa[i].z * sa[i].z));
            d[3] = __uint_as_float(f2tf32(pa[i].w * sa[i].w));
        }
#pragma unroll
        for (int i = 0; i < 2; ++i) {
            float* d = &Bs[(lr + i * 32) * 36 + lk];
            d[0] = __uint_as_float(f2tf32(pb[i].x));
            d[1] = __uint_as_float(f2tf32(pb[i].y));
            d[2] = __uint_as_float(f2tf32(pb[i].z));
            d[3] = __uint_as_float(f2tf32(pb[i].w));
        }
        __syncthreads();

        if (k0 + 32 < DD) {
#pragma unroll
            for (int i = 0; i < 4; ++i) {
                pa[i] = *(const float4*)(aptr + k0 + 32 + (size_t)i * 32 * DD);
                sa[i] = *(const float4*)(g_a + brow[i] * DD + k0 + 32 + lk);
            }
#pragma unroll
            for (int i = 0; i < 2; ++i) pb[i] = *(const float4*)(bptr + k0 + 32 + (size_t)i * 32 * DD);
        }

#pragma unroll
        for (int kk = 0; kk < 4; ++kk) {
            uint32_t af[2][4], bf[4][2];
#pragma unroll
            for (int mt = 0; mt < 2; ++mt) {
                const float* s = &As[(wm * 32 + mt * 16 + qid) * 36 + kk * 8 + tig];
                af[mt][0] = __float_as_uint(s[0]);
                af[mt][1] = __float_as_uint(s[8 * 36]);
                af[mt][2] = __float_as_uint(s[4]);
                af[mt][3] = __float_as_uint(s[8 * 36 + 4]);
            }
#pragma unroll
            for (int nt = 0; nt < 4; ++nt) {
                const float* s = &Bs[(wn * 32 + nt * 8 + qid) * 36 + kk * 8 + tig];
                bf[nt][0] = __float_as_uint(s[0]);
                bf[nt][1] = __float_as_uint(s[4]);
            }
#pragma unroll
            for (int mt = 0; mt < 2; ++mt)
#pragma unroll
                for (int nt = 0; nt < 4; ++nt)
                    mma8(acc[mt][nt], af[mt][0], af[mt][1], af[mt][2], af[mt][3],
                         bf[nt][0], bf[nt][1]);
        }
        __syncthreads();
    }

#pragma unroll
    for (int mt = 0; mt < 2; ++mt) {
        const int m = m0 + wm * 32 + mt * 16 + qid;
#pragma unroll
        for (int nt = 0; nt < 4; ++nt) {
            const int n = n0 + wn * 32 + nt * 8 + 2 * tig;
            const float bb0 = b1[n] + b2[n];
            const float bb1 = b1[n + 1] + b2[n + 1];
            float2 o0 = {acc[mt][nt][0] + bb0, acc[mt][nt][1] + bb1};
            float2 o1 = {acc[mt][nt][2] + bb0, acc[mt][nt][3] + bb1};
            *(float2*)(C + (size_t)m * G4 + n)       = o0;
            *(float2*)(C + (size_t)(m + 8) * G4 + n) = o1;
        }
    }
}

// ============================================================
// Kernel 3: PERSISTENT fp16 recurrence, latency-minimized.
// 128 blocks = 8 batch groups x 16 unit slices; block tile
// 32 batch x 128 gate-cols, K=512. Whh resident in smem (fp16).
// Warp-autonomous barrier polling; contiguous K-split: set 0
// loads+consumes chunks 0-3, set 1 chunks 4-7 — each set syncs
// on its own named barrier. Only 2 block-wide syncs per step.
// ============================================================
#define WHH_H  (128 * 520)                // Whh slice, fp16 halves
#define HCH_H  (32 * 72)                  // one 64-K h chunk, fp16 halves
#define GX_F   (32 * 132)                 // Gx tile, f32
#define GT_F   (2 * 32 * 132)             // 2-plane partial-sum exchange, f32
#define SMEM_REC (WHH_H * 2 + 8 * HCH_H * 2 + GX_F * 4 + GT_F * 4)  // 220672 B

__global__ void __launch_bounds__(256, 1) rec_persistent(
    const float* __restrict__ h0,
    const float* __restrict__ c0,
    const float* __restrict__ Whh,
    const float* __restrict__ Gx,
    float* __restrict__ enc,
    __half* __restrict__ hbuf)
{
    extern __shared__ __align__(16) __half smh[];
    __half* WhhS = smh;                         // [128][520]
    __half* hS   = smh + WHH_H;                 // [8][32][72]
    float*  GxS  = (float*)(smh + WHH_H + 8 * HCH_H);  // [32][132]
    float*  Gt   = GxS + GX_F;                  // [2][32][132]

    const int tid  = threadIdx.x;
    const int lane = tid & 31, warp = tid >> 5;
    const int qid  = lane >> 2, tig = lane & 3;
    const int set  = warp >> 2;                 // K half: 0 -> chunks 0-3, 1 -> 4-7
    const int gate = warp & 3;                  // 32-col group
    const int bid  = blockIdx.x;
    const int grp  = bid >> 4;                  // batch group 0..7
    const int m0   = grp * MB;
    const int u0   = (bid & 15) * UB;

    // ---- Whh slice -> smem fp16 (once) ----
    for (int idx = tid; idx < 128 * 128; idx += 256) {
        const int r = idx >> 7, kq = (idx & 127) * 4;
        const float4 v = *(const float4*)&Whh[(size_t)((r >> 5) * HH + u0 + (r & 31)) * HH + kq];
        *(__half2*)&WhhS[r * 520 + kq]     = __floats2half2_rn(v.x, v.y);
        *(__half2*)&WhhS[r * 520 + kq + 2] = __floats2half2_rn(v.z, v.w);
    }

    // ---- h(0) slice -> fp16 ping buffer 0 ----
    for (int idx = tid; idx < MB * UB; idx += 256) {
        const int b = idx >> 5, uu = idx & 31;
        hbuf[(size_t)(m0 + b) * HH + u0 + uu] =
            __float2half_rn(h0[(size_t)(m0 + b) * HH + u0 + uu]);
    }

    // ---- c slice in registers ----
    const int cb = tid >> 3;                    // 0..31 (batch rel)
    const int cu = (tid & 7) * 4;               // unit rel, step 4
    float creg[4];
    {
        const float4 cv = *(const float4*)&c0[(size_t)(m0 + cb) * HH + u0 + cu];
        creg[0] = cv.x; creg[1] = cv.y; creg[2] = cv.z; creg[3] = cv.w;
    }

    __syncthreads();                            // h(0)+Whh writes done block-wide
    if (tid == 0) bar_arrive(&g_ctr[grp][0]);   // publish h(0)

    // per-set h-load indices: 128 threads cover 4 chunks x 4KB
    const int stid = tid & 127;
    const int hr = stid >> 2;                   // row 0..31
    const int hq = (stid & 3) * 8;              // halves 0,8,16,24 (+32 second load)

    for (int t = 0; t < LL; ++t) {
        const __half* hsrc = hbuf + (size_t)(t & 1) * BB * HH;
        __half*       hdst = hbuf + (size_t)((t + 1) & 1) * BB * HH;

        // Gx prefetch for this step (static input; overlaps barrier wait)
        {
            const float* gbase = Gx + ((size_t)m0 * LL + t) * G4 + u0;
#pragma unroll
            for (int i = 0; i < 4; ++i) {
                const int idx = tid + i * 256;
                const int b = idx >> 5, g = (idx >> 3) & 3, q = (idx & 7) * 4;
                cpa16(&GxS[b * 132 + g * 32 + q],
                      gbase + (size_t)b * LL * G4 + g * HH + q);
            }
            CPA_COMMIT();
        }

        // ---- per-WARP barrier poll: h(t) ready from the 16 peer blocks ----
        if (lane == 0) {
            const unsigned* ctr = &g_ctr[grp][t];
            while (ld_acq(ctr) < 16u) {}
        }
        __syncwarp();

        // ---- this set loads ITS 4 chunks (16 KB), syncs on named barrier ----
#pragma unroll
        for (int j = 0; j < 4; ++j) {
            const int p = set * 4 + j;
            const __half* src = hsrc + (size_t)(m0 + hr) * HH + p * 64;
            cpa16(&hS[p * HCH_H + hr * 72 + hq],      src + hq);
            cpa16(&hS[p * HCH_H + hr * 72 + hq + 32], src + hq + 32);
        }
        CPA_COMMIT();
        CPA_WAIT0();                            // drains Gx group too
        asm volatile("bar.sync %0, %1;" :: "r"(1 + set), "r"(128) : "memory");

        // ---- sync-free MMA loop on this set's contiguous K half ----
        float acc[2][4][4] = {};
#pragma unroll
        for (int j = 0; j < 4; ++j) {
            const int kc = set * 4 + j;
            const __half* hA = hS + kc * HCH_H;
            const __half* wB = WhhS + kc * 64;
#pragma unroll
            for (int kk = 0; kk < 4; ++kk) {
                uint32_t af[2][4], bf[4][2];
#pragma unroll
                for (int mt = 0; mt < 2; ++mt) {
                    const __half* s = hA + (mt * 16 + qid) * 72 + kk * 16 + tig * 2;
                    af[mt][0] = *(const uint32_t*)(s);
                    af[mt][1] = *(const uint32_t*)(s + 8 * 72);
                    af[mt][2] = *(const uint32_t*)(s + 8);
                    af[mt][3] = *(const uint32_t*)(s + 8 * 72 + 8);
                }
#pragma unroll
                for (int nt = 0; nt < 4; ++nt) {
                    const __half* s = wB + (gate * 32 + nt * 8 + qid) * 520 + kk * 16 + tig * 2;
                    bf[nt][0] = *(const uint32_t*)(s);
                    bf[nt][1] = *(const uint32_t*)(s + 8);
                }
#pragma unroll
                for (int mt = 0; mt < 2; ++mt)
#pragma unroll
                    for (int nt = 0; nt < 4; ++nt)
                        mma16(acc[mt][nt], af[mt][0], af[mt][1], af[mt][2], af[mt][3],
                              bf[nt][0], bf[nt][1]);
            }
        }

        // ---- epilogue: partials -> 2-plane Gt (disjoint per set) ----
        {
            float* Gp = Gt + set * (32 * 132);
#pragma unroll
            for (int mt = 0; mt < 2; ++mt) {
                const int rl = mt * 16 + qid;
#pragma unroll
                for (int nt = 0; nt < 4; ++nt) {
                    const int cl = gate * 32 + nt * 8 + tig * 2;
                    *(float2*)&Gp[rl * 132 + cl]       = make_float2(acc[mt][nt][0], acc[mt][nt][1]);
                    *(float2*)&Gp[(rl + 8) * 132 + cl] = make_float2(acc[mt][nt][2], acc[mt][nt][3]);
                }
            }
        }
        __syncthreads();                        // block sync #1: Gt complete

        // ---- LSTM cell: sum partials + Gx; fast transcendentals ----
        {
            float gv[4][4];
#pragma unroll
            for (int g = 0; g < 4; ++g) {
                const int off = cb * 132 + g * 32 + cu;
                const float4 p0 = *(const float4*)&Gt[off];
                const float4 p1 = *(const float4*)&Gt[32 * 132 + off];
                const float4 px = *(const float4*)&GxS[off];
                gv[g][0] = p0.x + p1.x + px.x;
                gv[g][1] = p0.y + p1.y + px.y;
                gv[g][2] = p0.z + p1.z + px.z;
                gv[g][3] = p0.w + p1.w + px.w;
            }

            float4 ho;
            float* hop = &ho.x;
            __half hr4[4];
#pragma unroll
            for (int k = 0; k < 4; ++k) {
                const float si = sigf(gv[0][k]);
                const float sf = sigf(gv[1][k]);
                const float so = sigf(gv[3][k]);
                const float cn = sf * creg[k] + si * tanhfast(gv[2][k]);
                const float hn = so * tanhfast(cn);
                creg[k] = cn;
                hop[k] = hn;
                hr4[k] = __float2half_rn(hn);
            }
            *(float4*)(enc + (size_t)(m0 + cb) * LL * HH + (size_t)t * HH + u0 + cu) = ho;
            *(uint2*)(hdst + (size_t)(m0 + cb) * HH + u0 + cu) = *(const uint2*)hr4;
        }
        __syncthreads();                        // block sync #2: hdst/Gt/GxS done
        if (tid == 0 && t + 1 < LL) bar_arrive(&g_ctr[grp][t + 1]);
    }
}

// ============================================================
// Launch
// ============================================================
extern "C" void kernel_launch(void* const* d_in, const int* in_sizes, int n_in,
                              void* d_out, int out_size)
{
    (void)in_sizes; (void)n_in; (void)out_size;
    const float* x   = (const float*)d_in[0];
    const float* h0  = (const float*)d_in[1];
    const float* c0  = (const float*)d_in[2];
    const float* Wih = (const float*)d_in[3];
    const float* Whh = (const float*)d_in[4];
    const float* bih = (const float*)d_in[5];
    const float* bhh = (const float*)d_in[6];
    const float* Wa  = (const float*)d_in[7];
    // d_in[8] = ba: cancels inside softmax, never read.

    float* att = (float*)d_out;                       // (B, L, D)
    float* enc = att + (size_t)BB * LL * DD;          // (B, L, H)

    float *gx;
    __half* hbuf;
    void* ctr;
    cudaGetSymbolAddress((void**)&gx,   g_Gx);
    cudaGetSymbolAddress((void**)&hbuf, g_h);
    cudaGetSymbolAddress(&ctr,          g_ctr);

    static int smem_set = 0;
    if (!smem_set) {
        cudaFuncSetAttribute(rec_persistent,
                             cudaFuncAttributeMaxDynamicSharedMemorySize, SMEM_REC);
        smem_set = 1;
    }

    // 0) zero per-step barrier counters (captured memset node)
    cudaMemsetAsync(ctr, 0, sizeof(unsigned) * NGRP * LL);

    // 1) attention weights a + att output
    attn_kernel<<<BB, DD>>>(x, Wa, att);

    // 2) input projection with fused a-scaling (tf32 tensor cores)
    {
        dim3 grid(G4 / 64, (BB * LL) / 128);
        gemm_xproj<<<grid, 256>>>(x, Wih, bih, bhh, gx);
    }

    // 3) whole recurrence in ONE persistent fp16 kernel
    rec_persistent<<<NBLK, 256, SMEM_REC>>>(h0, c0, Whh, gx, enc, hbuf);
}